// round 1
// baseline (speedup 1.0000x reference)
#include <cuda_runtime.h>
#include <math.h>

// Problem constants
#define BATCH   16
#define SEQ     1024
#define HID     1024
#define NHEADS  16
#define HDIM    64
#define ROWS    (BATCH * SEQ)          // 16384

// Scratch (device globals: allocation is forbidden)
__device__ float g_q[BATCH * NHEADS * SEQ * HDIM];  // [b][h][n][d]
__device__ float g_k[BATCH * NHEADS * SEQ * HDIM];
__device__ float g_v[BATCH * NHEADS * SEQ * HDIM];
__device__ float g_o[ROWS * HID];                   // [b*n][h*d] row-major

// ---------------------------------------------------------------------------
// 128x128x8 SIMT fp32 GEMM, 256 threads, 8x8 per thread.
// MODE 0/1/2: A = x (param), Out = g_q/g_k/g_v in [b,head,n,d] layout.
// MODE 3:     A = g_o, Out = param (row-major), for the output projection.
// ---------------------------------------------------------------------------
template <int MODE>
__global__ __launch_bounds__(256) void gemm128(const float* __restrict__ A,
                                               const float* __restrict__ W,
                                               const float* __restrict__ bias,
                                               float* __restrict__ OutParam)
{
    __shared__ float As[8][132];   // A^T tile: As[k][m], pad 132 -> conflict-free
    __shared__ float Bs[8][128];   // W tile:   Bs[k][n]

    const float* Abase = (MODE == 3) ? (const float*)g_o : A;
    float* Op;
    if      (MODE == 0) Op = g_q;
    else if (MODE == 1) Op = g_k;
    else if (MODE == 2) Op = g_v;
    else                Op = OutParam;

    const int tid = threadIdx.x;
    const int m0 = blockIdx.y * 128;
    const int n0 = blockIdx.x * 128;
    const int ty = tid >> 4;          // 0..15
    const int tx = tid & 15;          // 0..15

    const int arow = tid >> 1;        // 0..127
    const int acol = (tid & 1) * 4;   // 0 or 4
    const int brow = tid >> 5;        // 0..7
    const int bcol = (tid & 31) * 4;  // 0..124

    const float* Ap = Abase + (size_t)(m0 + arow) * HID + acol;
    const float* Bp = W + (size_t)brow * HID + n0 + bcol;

    float acc[8][8];
#pragma unroll
    for (int i = 0; i < 8; i++)
#pragma unroll
        for (int j = 0; j < 8; j++) acc[i][j] = 0.0f;

    for (int k0 = 0; k0 < HID; k0 += 8) {
        float4 a = *(const float4*)(Ap + k0);
        float4 b = *(const float4*)(Bp + (size_t)k0 * HID);
        __syncthreads();
        As[acol + 0][arow] = a.x;
        As[acol + 1][arow] = a.y;
        As[acol + 2][arow] = a.z;
        As[acol + 3][arow] = a.w;
        *(float4*)&Bs[brow][bcol] = b;
        __syncthreads();
#pragma unroll
        for (int kk = 0; kk < 8; kk++) {
            float4 a0 = *(const float4*)&As[kk][ty * 4];
            float4 a1 = *(const float4*)&As[kk][64 + ty * 4];
            float4 b0 = *(const float4*)&Bs[kk][tx * 4];
            float4 b1 = *(const float4*)&Bs[kk][64 + tx * 4];
            float av[8] = {a0.x, a0.y, a0.z, a0.w, a1.x, a1.y, a1.z, a1.w};
            float bv[8] = {b0.x, b0.y, b0.z, b0.w, b1.x, b1.y, b1.z, b1.w};
#pragma unroll
            for (int i = 0; i < 8; i++)
#pragma unroll
                for (int j = 0; j < 8; j++)
                    acc[i][j] += av[i] * bv[j];
        }
    }

    // Epilogue with bias
    float4 bias0 = *(const float4*)(bias + n0 + tx * 4);
    float4 bias1 = *(const float4*)(bias + n0 + 64 + tx * 4);
    float bb[8] = {bias0.x, bias0.y, bias0.z, bias0.w,
                   bias1.x, bias1.y, bias1.z, bias1.w};

#pragma unroll
    for (int i = 0; i < 8; i++) {
        int m = m0 + ((i < 4) ? (ty * 4 + i) : (64 + ty * 4 + (i - 4)));
#pragma unroll
        for (int jh = 0; jh < 2; jh++) {
            int c = n0 + jh * 64 + tx * 4;
            float4 v;
            v.x = acc[i][jh * 4 + 0] + bb[jh * 4 + 0];
            v.y = acc[i][jh * 4 + 1] + bb[jh * 4 + 1];
            v.z = acc[i][jh * 4 + 2] + bb[jh * 4 + 2];
            v.w = acc[i][jh * 4 + 3] + bb[jh * 4 + 3];
            if (MODE < 3) {
                int bidx = m >> 10;            // batch
                int n    = m & (SEQ - 1);      // seq pos
                int head = c >> 6;             // head
                int d    = c & (HDIM - 1);     // dim within head
                *(float4*)(Op + ((((size_t)bidx * NHEADS + head) * SEQ + n) * HDIM + d)) = v;
            } else {
                *(float4*)(Op + (size_t)m * HID + c) = v;
            }
        }
    }
}

// ---------------------------------------------------------------------------
// Flash attention: one CTA per (batch, head, 64-query tile).
// Q,K stored d-major in smem (stride 68, 16B aligned rows) -> S phase is
// two conflict-free LDS.128 + 16 FFMA per thread per d-step.
// V natural layout, P staged in smem for the PV phase.
// ---------------------------------------------------------------------------
#define FS 68                          // smem row stride (floats)
#define FLASH_SMEM (4 * 64 * FS * 4)   // Qt, Kt, Vs, Ps = 69632 B

__global__ __launch_bounds__(256) void flash_kernel()
{
    extern __shared__ float sm[];
    float* Qt = sm;                 // [d][q]  64 x FS
    float* Kt = sm + 64 * FS;       // [d][k]
    float* Vs = sm + 2 * 64 * FS;   // [k][d]
    float* Ps = sm + 3 * 64 * FS;   // [q][k]

    const int tid = threadIdx.x;
    const int tx = tid & 15;        // 0..15 (key-col / d-col group)
    const int ty = tid >> 4;        // 0..15 (query-row group)

    const int b  = blockIdx.z;
    const int h  = blockIdx.y;
    const int q0 = blockIdx.x * 64;

    const float* __restrict__ Qg = g_q + (((size_t)b * NHEADS + h) * SEQ + q0) * HDIM;
    const float* __restrict__ Kg = g_k + (((size_t)b * NHEADS + h) * SEQ) * HDIM;
    const float* __restrict__ Vg = g_v + (((size_t)b * NHEADS + h) * SEQ) * HDIM;

    const float scale = 0.125f;     // 1/sqrt(64)

    // Load Q tile transposed (pre-scaled)
#pragma unroll
    for (int p = 0; p < 4; p++) {
        int r = ty + p * 16;        // query row
        float4 a = *(const float4*)(Qg + (size_t)r * HDIM + tx * 4);
        Qt[(tx * 4 + 0) * FS + r] = a.x * scale;
        Qt[(tx * 4 + 1) * FS + r] = a.y * scale;
        Qt[(tx * 4 + 2) * FS + r] = a.z * scale;
        Qt[(tx * 4 + 3) * FS + r] = a.w * scale;
    }

    float o[4][4];
    float mrow[4], lrow[4];
#pragma unroll
    for (int i = 0; i < 4; i++) {
        mrow[i] = -1e30f;
        lrow[i] = 0.0f;
#pragma unroll
        for (int j = 0; j < 4; j++) o[i][j] = 0.0f;
    }

    for (int kt = 0; kt < 16; kt++) {
        const int k0 = kt * 64;
        __syncthreads();   // previous PV done (and Qt visible on first iter)

        // Load K tile (transposed) and V tile (natural)
#pragma unroll
        for (int p = 0; p < 4; p++) {
            int r = ty + p * 16;
            float4 kv = *(const float4*)(Kg + (size_t)(k0 + r) * HDIM + tx * 4);
            Kt[(tx * 4 + 0) * FS + r] = kv.x;
            Kt[(tx * 4 + 1) * FS + r] = kv.y;
            Kt[(tx * 4 + 2) * FS + r] = kv.z;
            Kt[(tx * 4 + 3) * FS + r] = kv.w;
            float4 vv = *(const float4*)(Vg + (size_t)(k0 + r) * HDIM + tx * 4);
            *(float4*)&Vs[r * FS + tx * 4] = vv;
        }
        __syncthreads();

        // S = Q K^T (4x4 per thread): rows 4ty+i, keys 4tx+j
        float s[4][4];
#pragma unroll
        for (int i = 0; i < 4; i++)
#pragma unroll
            for (int j = 0; j < 4; j++) s[i][j] = 0.0f;

#pragma unroll 8
        for (int d = 0; d < 64; d++) {
            float4 qv = *(const float4*)&Qt[d * FS + ty * 4];
            float4 kv = *(const float4*)&Kt[d * FS + tx * 4];
            float qa[4] = {qv.x, qv.y, qv.z, qv.w};
            float ka[4] = {kv.x, kv.y, kv.z, kv.w};
#pragma unroll
            for (int i = 0; i < 4; i++)
#pragma unroll
                for (int j = 0; j < 4; j++)
                    s[i][j] += qa[i] * ka[j];
        }

        // Online softmax: reductions across the 16 tx lanes sharing each row
#pragma unroll
        for (int i = 0; i < 4; i++) {
            float tm = fmaxf(fmaxf(s[i][0], s[i][1]), fmaxf(s[i][2], s[i][3]));
#pragma unroll
            for (int off = 8; off >= 1; off >>= 1)
                tm = fmaxf(tm, __shfl_xor_sync(0xffffffffu, tm, off, 16));
            float mnew  = fmaxf(mrow[i], tm);
            float alpha = __expf(mrow[i] - mnew);
            float rs = 0.0f;
#pragma unroll
            for (int j = 0; j < 4; j++) {
                s[i][j] = __expf(s[i][j] - mnew);
                rs += s[i][j];
            }
#pragma unroll
            for (int off = 8; off >= 1; off >>= 1)
                rs += __shfl_xor_sync(0xffffffffu, rs, off, 16);
            lrow[i] = lrow[i] * alpha + rs;
            mrow[i] = mnew;
#pragma unroll
            for (int j = 0; j < 4; j++) {
                o[i][j] *= alpha;
                Ps[(ty * 4 + i) * FS + tx * 4 + j] = s[i][j];
            }
        }
        __syncthreads();

        // O += P @ V  (O rows 4ty+i, dims 4tx+j)
#pragma unroll 8
        for (int k = 0; k < 64; k++) {
            float4 vv = *(const float4*)&Vs[k * FS + tx * 4];
            float va[4] = {vv.x, vv.y, vv.z, vv.w};
#pragma unroll
            for (int i = 0; i < 4; i++) {
                float p = Ps[(ty * 4 + i) * FS + k];
#pragma unroll
                for (int j = 0; j < 4; j++)
                    o[i][j] += p * va[j];
            }
        }
    }

    // Epilogue: normalize, write to g_o in [b*n][h*64+d] layout
    float* Og = g_o + ((size_t)b * SEQ + q0) * HID + h * HDIM;
#pragma unroll
    for (int i = 0; i < 4; i++) {
        float inv = 1.0f / lrow[i];
        float4 v;
        v.x = o[i][0] * inv;
        v.y = o[i][1] * inv;
        v.z = o[i][2] * inv;
        v.w = o[i][3] * inv;
        *(float4*)(Og + (size_t)(ty * 4 + i) * HID + tx * 4) = v;
    }
}

// ---------------------------------------------------------------------------
extern "C" void kernel_launch(void* const* d_in, const int* in_sizes, int n_in,
                              void* d_out, int out_size)
{
    const float* x  = (const float*)d_in[0];
    const float* wq = (const float*)d_in[1];
    const float* bq = (const float*)d_in[2];
    const float* wk = (const float*)d_in[3];
    const float* bk = (const float*)d_in[4];
    const float* wv = (const float*)d_in[5];
    const float* bv = (const float*)d_in[6];
    const float* wo = (const float*)d_in[7];
    const float* bo = (const float*)d_in[8];
    float* out = (float*)d_out;

    dim3 blk(256);
    dim3 grid(HID / 128, ROWS / 128);   // (8, 128)

    gemm128<0><<<grid, blk>>>(x, wq, bq, nullptr);
    gemm128<1><<<grid, blk>>>(x, wk, bk, nullptr);
    gemm128<2><<<grid, blk>>>(x, wv, bv, nullptr);

    cudaFuncSetAttribute(flash_kernel,
                         cudaFuncAttributeMaxDynamicSharedMemorySize, FLASH_SMEM);
    flash_kernel<<<dim3(SEQ / 64, NHEADS, BATCH), blk, FLASH_SMEM>>>();

    gemm128<3><<<grid, blk>>>(nullptr, wo, bo, out);
}

// round 3
// speedup vs baseline: 1.6444x; 1.6444x over previous
#include <cuda_runtime.h>
#include <cuda_bf16.h>
#include <stdint.h>
#include <math.h>

// Problem constants
#define BATCH   16
#define SEQ     1024
#define HID     1024
#define NHEADS  16
#define HDIM    64
#define ROWS    (BATCH * SEQ)          // 16384

// ---------------------------------------------------------------------------
// Scratch (device globals: allocation is forbidden)
// ---------------------------------------------------------------------------
__device__ float g_q[BATCH * NHEADS * SEQ * HDIM];  // [b][h][n][d]
__device__ float g_k[BATCH * NHEADS * SEQ * HDIM];
__device__ float g_v[BATCH * NHEADS * SEQ * HDIM];
__device__ float g_o[ROWS * HID];                   // [b*n][h*d] row-major

__device__ __nv_bfloat16 g_ah[ROWS * HID];          // activation hi (x or g_o)
__device__ __nv_bfloat16 g_al[ROWS * HID];          // activation lo
__device__ __nv_bfloat16 g_bh[HID * HID];           // weight^T hi  [n][k]
__device__ __nv_bfloat16 g_bl[HID * HID];           // weight^T lo  [n][k]

// ---------------------------------------------------------------------------
// PTX helpers
// ---------------------------------------------------------------------------
__device__ __forceinline__ uint32_t smem_u32(const void* p) {
    uint32_t a;
    asm("{ .reg .u64 t; cvta.to.shared.u64 t, %1; cvt.u32.u64 %0, t; }"
        : "=r"(a) : "l"(p));
    return a;
}

__device__ __forceinline__ void cp16(uint32_t dst, const void* src) {
    asm volatile("cp.async.cg.shared.global [%0], [%1], 16;" :: "r"(dst), "l"(src) : "memory");
}
#define CP_COMMIT() asm volatile("cp.async.commit_group;" ::: "memory")
#define CP_WAIT1()  asm volatile("cp.async.wait_group 1;" ::: "memory")
#define CP_WAIT0()  asm volatile("cp.async.wait_group 0;" ::: "memory")

__device__ __forceinline__ void ldsm4(uint32_t* r, uint32_t addr) {
    asm volatile("ldmatrix.sync.aligned.m8n8.x4.shared.b16 {%0,%1,%2,%3}, [%4];"
        : "=r"(r[0]), "=r"(r[1]), "=r"(r[2]), "=r"(r[3]) : "r"(addr));
}

__device__ __forceinline__ void mma16816(float* c, const uint32_t* a, const uint32_t* b) {
    asm volatile("mma.sync.aligned.m16n8k16.row.col.f32.bf16.bf16.f32 "
        "{%0,%1,%2,%3}, {%4,%5,%6,%7}, {%8,%9}, {%0,%1,%2,%3};"
        : "+f"(c[0]), "+f"(c[1]), "+f"(c[2]), "+f"(c[3])
        : "r"(a[0]), "r"(a[1]), "r"(a[2]), "r"(a[3]), "r"(b[0]), "r"(b[1]));
}

// ---------------------------------------------------------------------------
// Split / transpose-split conversion kernels
// ---------------------------------------------------------------------------
template <bool FROM_GO>
__global__ __launch_bounds__(256) void split_act(const float* __restrict__ srcp) {
    const float* src = FROM_GO ? (const float*)g_o : srcp;
    int i = blockIdx.x * 256 + threadIdx.x;     // float4 index
    float4 a = ((const float4*)src)[i];
    __nv_bfloat16 h0 = __float2bfloat16(a.x);
    __nv_bfloat16 h1 = __float2bfloat16(a.y);
    __nv_bfloat16 h2 = __float2bfloat16(a.z);
    __nv_bfloat16 h3 = __float2bfloat16(a.w);
    __nv_bfloat16 l0 = __float2bfloat16(a.x - __bfloat162float(h0));
    __nv_bfloat16 l1 = __float2bfloat16(a.y - __bfloat162float(h1));
    __nv_bfloat16 l2 = __float2bfloat16(a.z - __bfloat162float(h2));
    __nv_bfloat16 l3 = __float2bfloat16(a.w - __bfloat162float(h3));
    ushort4 H, L;
    H.x = *(unsigned short*)&h0; H.y = *(unsigned short*)&h1;
    H.z = *(unsigned short*)&h2; H.w = *(unsigned short*)&h3;
    L.x = *(unsigned short*)&l0; L.y = *(unsigned short*)&l1;
    L.z = *(unsigned short*)&l2; L.w = *(unsigned short*)&l3;
    ((ushort4*)g_ah)[i] = H;
    ((ushort4*)g_al)[i] = L;
}

// W[k][n] (fp32) -> Wt_hi/lo[n][k] (bf16)
__global__ __launch_bounds__(256) void wsplit(const float* __restrict__ W) {
    __shared__ float t[32][33];
    int x0 = blockIdx.x * 32, y0 = blockIdx.y * 32;
    int tx = threadIdx.x, ty = threadIdx.y;     // block (32, 8)
#pragma unroll
    for (int j = ty; j < 32; j += 8)
        t[j][tx] = W[(size_t)(y0 + j) * HID + x0 + tx];
    __syncthreads();
#pragma unroll
    for (int j = ty; j < 32; j += 8) {
        float v = t[tx][j];                     // = W[y0+tx][x0+j]
        __nv_bfloat16 h = __float2bfloat16(v);
        __nv_bfloat16 l = __float2bfloat16(v - __bfloat162float(h));
        g_bh[(size_t)(x0 + j) * HID + y0 + tx] = h;
        g_bl[(size_t)(x0 + j) * HID + y0 + tx] = l;
    }
}

// ---------------------------------------------------------------------------
// mma.sync split-bf16 GEMM: C[16384,1024] = A @ W + bias
// CTA: 128x128 tile, 8 warps (2x4), warp tile 64x32, K staged 64/stage,
// 3 passes (Ah*Bh, Al*Bh, Ah*Bl). MODE 0/1/2 -> g_q/g_k/g_v [b,h,n,d];
// MODE 3 -> row-major OutParam.
// ---------------------------------------------------------------------------
#define SM_BIAS   64
#define SM_BUF    1024
#define STAGE_B   32768                     // A 16KB + B 16KB
#define GEMM_SMEM (SM_BUF + 2 * STAGE_B)
#define NSTAGES   48

__device__ __forceinline__ void load_stage(uint32_t sb, int s, int buf,
                                           int m0, int n0, int tid) {
    const int pass = s >> 4, kc = s & 15;
    const __nv_bfloat16* Ap = (pass == 1) ? g_al : g_ah;
    const __nv_bfloat16* Bp = (pass == 2) ? g_bl : g_bh;
    const int k = kc * 64;
    const uint32_t ab = sb + SM_BUF + buf * STAGE_B;
    const uint32_t bb = ab + 16384;
#pragma unroll
    for (int it = 0; it < 4; it++) {
        int c = it * 256 + tid;                 // 0..1023 chunk id
        int row = c >> 3;
        int col = (c & 7) * 16;                 // byte offset in 128B row
        uint32_t off = (uint32_t)(row * 128 + col);
        uint32_t swo = off ^ ((off >> 3) & 0x70);
        cp16(ab + swo, (const char*)(Ap + (size_t)(m0 + row) * HID + k) + col);
        cp16(bb + swo, (const char*)(Bp + (size_t)(n0 + row) * HID + k) + col);
    }
}

template <int MODE>
__global__ __launch_bounds__(256, 2) void tc_gemm(const float* __restrict__ bias,
                                                  float* __restrict__ OutParam) {
    extern __shared__ char smem[];
    const uint32_t sb = smem_u32(smem);
    const int tid = threadIdx.x, wid = tid >> 5, lane = tid & 31;
    const int n0 = blockIdx.x * 128, m0 = blockIdx.y * 128;
    const int wm = wid & 1, wn = wid >> 1;      // warp grid 2(m) x 4(n)
    float* sbias = (float*)(smem + SM_BIAS);

    if (tid < 128) sbias[tid] = bias[n0 + tid];

    float acc[4][4][4];
#pragma unroll
    for (int i = 0; i < 4; i++)
#pragma unroll
        for (int j = 0; j < 4; j++)
#pragma unroll
            for (int r = 0; r < 4; r++) acc[i][j][r] = 0.0f;

    // ldmatrix per-thread row/col bases (within tile, before swizzle)
    const int r8 = lane & 7, midx = lane >> 3;
    // A x4: m0: rows0-7 k0 | m1: rows8-15 k0 | m2: rows0-7 k8 | m3: rows8-15 k8
    const int a_row_base = wm * 64 + (midx & 1) * 8 + r8;
    const int a_c16_base = (midx >> 1);
    // B x4: m0: n0-7 k0 | m1: n0-7 k8 | m2: n8-15 k0 | m3: n8-15 k8
    const int b_row_base = wn * 32 + (midx >> 1) * 8 + r8;
    const int b_c16_base = (midx & 1);

    // Prologue
    load_stage(sb, 0, 0, m0, n0, tid);
    CP_COMMIT();

    for (int s = 0; s < NSTAGES; s++) {
        const int cur = s & 1;
        if (s + 1 < NSTAGES) {
            load_stage(sb, s + 1, cur ^ 1, m0, n0, tid);
            CP_COMMIT();
            CP_WAIT1();
        } else {
            CP_WAIT0();
        }
        __syncthreads();

        const uint32_t abase = sb + SM_BUF + cur * STAGE_B;
        const uint32_t bbase = abase + 16384;
#pragma unroll
        for (int ks = 0; ks < 4; ks++) {
            uint32_t af[4][4], bf[2][4];
#pragma unroll
            for (int i = 0; i < 4; i++) {
                int row = a_row_base + i * 16;
                int c16 = ks * 2 + a_c16_base;
                ldsm4(af[i], abase + (uint32_t)(row * 128 + ((c16 ^ (row & 7)) * 16)));
            }
#pragma unroll
            for (int jj = 0; jj < 2; jj++) {
                int row = b_row_base + jj * 16;
                int c16 = ks * 2 + b_c16_base;
                ldsm4(bf[jj], bbase + (uint32_t)(row * 128 + ((c16 ^ (row & 7)) * 16)));
            }
#pragma unroll
            for (int i = 0; i < 4; i++)
#pragma unroll
                for (int j = 0; j < 4; j++)
                    mma16816(acc[i][j], af[i], &bf[j >> 1][(j & 1) * 2]);
        }
        __syncthreads();
    }

    // Epilogue: register fragments -> global (bias added)
    const int rq = lane >> 2, cq = (lane & 3) * 2;
#pragma unroll
    for (int i = 0; i < 4; i++) {
#pragma unroll
        for (int j = 0; j < 4; j++) {
            int cc = wn * 32 + j * 8 + cq;          // col within 128 tile
            float b0 = sbias[cc], b1 = sbias[cc + 1];
            int mrow = m0 + wm * 64 + i * 16 + rq;
            if (MODE < 3) {
                float* outp = (MODE == 0) ? g_q : (MODE == 1) ? g_k : g_v;
                int c_g  = n0 + cc;
                int head = c_g >> 6, d = c_g & 63;
                int b_   = mrow >> 10;
                int nn   = mrow & (SEQ - 1);
                float* dst = outp + (((size_t)b_ * NHEADS + head) * SEQ + nn) * HDIM + d;
                float2 v0 = {acc[i][j][0] + b0, acc[i][j][1] + b1};
                float2 v1 = {acc[i][j][2] + b0, acc[i][j][3] + b1};
                *(float2*)dst = v0;
                *(float2*)(dst + 8 * HDIM) = v1;
            } else {
                float* dst = OutParam + (size_t)mrow * HID + n0 + cc;
                float2 v0 = {acc[i][j][0] + b0, acc[i][j][1] + b1};
                float2 v1 = {acc[i][j][2] + b0, acc[i][j][3] + b1};
                *(float2*)dst = v0;
                *(float2*)(dst + 8 * HID) = v1;
            }
        }
    }
}

// ---------------------------------------------------------------------------
// Flash attention (unchanged): one CTA per (batch, head, 64-q tile)
// ---------------------------------------------------------------------------
#define FS 68
#define FLASH_SMEM (4 * 64 * FS * 4)

__global__ __launch_bounds__(256) void flash_kernel()
{
    extern __shared__ float sm[];
    float* Qt = sm;
    float* Kt = sm + 64 * FS;
    float* Vs = sm + 2 * 64 * FS;
    float* Ps = sm + 3 * 64 * FS;

    const int tid = threadIdx.x;
    const int tx = tid & 15;
    const int ty = tid >> 4;

    const int b  = blockIdx.z;
    const int h  = blockIdx.y;
    const int q0 = blockIdx.x * 64;

    const float* __restrict__ Qg = g_q + (((size_t)b * NHEADS + h) * SEQ + q0) * HDIM;
    const float* __restrict__ Kg = g_k + (((size_t)b * NHEADS + h) * SEQ) * HDIM;
    const float* __restrict__ Vg = g_v + (((size_t)b * NHEADS + h) * SEQ) * HDIM;

    const float scale = 0.125f;

#pragma unroll
    for (int p = 0; p < 4; p++) {
        int r = ty + p * 16;
        float4 a = *(const float4*)(Qg + (size_t)r * HDIM + tx * 4);
        Qt[(tx * 4 + 0) * FS + r] = a.x * scale;
        Qt[(tx * 4 + 1) * FS + r] = a.y * scale;
        Qt[(tx * 4 + 2) * FS + r] = a.z * scale;
        Qt[(tx * 4 + 3) * FS + r] = a.w * scale;
    }

    float o[4][4];
    float mrow[4], lrow[4];
#pragma unroll
    for (int i = 0; i < 4; i++) {
        mrow[i] = -1e30f;
        lrow[i] = 0.0f;
#pragma unroll
        for (int j = 0; j < 4; j++) o[i][j] = 0.0f;
    }

    for (int kt = 0; kt < 16; kt++) {
        const int k0 = kt * 64;
        __syncthreads();

#pragma unroll
        for (int p = 0; p < 4; p++) {
            int r = ty + p * 16;
            float4 kv = *(const float4*)(Kg + (size_t)(k0 + r) * HDIM + tx * 4);
            Kt[(tx * 4 + 0) * FS + r] = kv.x;
            Kt[(tx * 4 + 1) * FS + r] = kv.y;
            Kt[(tx * 4 + 2) * FS + r] = kv.z;
            Kt[(tx * 4 + 3) * FS + r] = kv.w;
            float4 vv = *(const float4*)(Vg + (size_t)(k0 + r) * HDIM + tx * 4);
            *(float4*)&Vs[r * FS + tx * 4] = vv;
        }
        __syncthreads();

        float s[4][4];
#pragma unroll
        for (int i = 0; i < 4; i++)
#pragma unroll
            for (int j = 0; j < 4; j++) s[i][j] = 0.0f;

#pragma unroll 8
        for (int d = 0; d < 64; d++) {
            float4 qv = *(const float4*)&Qt[d * FS + ty * 4];
            float4 kv = *(const float4*)&Kt[d * FS + tx * 4];
            float qa[4] = {qv.x, qv.y, qv.z, qv.w};
            float ka[4] = {kv.x, kv.y, kv.z, kv.w};
#pragma unroll
            for (int i = 0; i < 4; i++)
#pragma unroll
                for (int j = 0; j < 4; j++)
                    s[i][j] += qa[i] * ka[j];
        }

#pragma unroll
        for (int i = 0; i < 4; i++) {
            float tm = fmaxf(fmaxf(s[i][0], s[i][1]), fmaxf(s[i][2], s[i][3]));
#pragma unroll
            for (int off = 8; off >= 1; off >>= 1)
                tm = fmaxf(tm, __shfl_xor_sync(0xffffffffu, tm, off, 16));
            float mnew  = fmaxf(mrow[i], tm);
            float alpha = __expf(mrow[i] - mnew);
            float rs = 0.0f;
#pragma unroll
            for (int j = 0; j < 4; j++) {
                s[i][j] = __expf(s[i][j] - mnew);
                rs += s[i][j];
            }
#pragma unroll
            for (int off = 8; off >= 1; off >>= 1)
                rs += __shfl_xor_sync(0xffffffffu, rs, off, 16);
            lrow[i] = lrow[i] * alpha + rs;
            mrow[i] = mnew;
#pragma unroll
            for (int j = 0; j < 4; j++) {
                o[i][j] *= alpha;
                Ps[(ty * 4 + i) * FS + tx * 4 + j] = s[i][j];
            }
        }
        __syncthreads();

#pragma unroll 8
        for (int k = 0; k < 64; k++) {
            float4 vv = *(const float4*)&Vs[k * FS + tx * 4];
            float va[4] = {vv.x, vv.y, vv.z, vv.w};
#pragma unroll
            for (int i = 0; i < 4; i++) {
                float p = Ps[(ty * 4 + i) * FS + k];
#pragma unroll
                for (int j = 0; j < 4; j++)
                    o[i][j] += p * va[j];
            }
        }
    }

    float* Og = g_o + ((size_t)b * SEQ + q0) * HID + h * HDIM;
#pragma unroll
    for (int i = 0; i < 4; i++) {
        float inv = 1.0f / lrow[i];
        float4 v;
        v.x = o[i][0] * inv;
        v.y = o[i][1] * inv;
        v.z = o[i][2] * inv;
        v.w = o[i][3] * inv;
        *(float4*)(Og + (size_t)(ty * 4 + i) * HID + tx * 4) = v;
    }
}

// ---------------------------------------------------------------------------
extern "C" void kernel_launch(void* const* d_in, const int* in_sizes, int n_in,
                              void* d_out, int out_size)
{
    const float* x  = (const float*)d_in[0];
    const float* wq = (const float*)d_in[1];
    const float* bq = (const float*)d_in[2];
    const float* wk = (const float*)d_in[3];
    const float* bk = (const float*)d_in[4];
    const float* wv = (const float*)d_in[5];
    const float* bv = (const float*)d_in[6];
    const float* wo = (const float*)d_in[7];
    const float* bo = (const float*)d_in[8];
    float* out = (float*)d_out;

    cudaFuncSetAttribute(tc_gemm<0>, cudaFuncAttributeMaxDynamicSharedMemorySize, GEMM_SMEM);
    cudaFuncSetAttribute(tc_gemm<1>, cudaFuncAttributeMaxDynamicSharedMemorySize, GEMM_SMEM);
    cudaFuncSetAttribute(tc_gemm<2>, cudaFuncAttributeMaxDynamicSharedMemorySize, GEMM_SMEM);
    cudaFuncSetAttribute(tc_gemm<3>, cudaFuncAttributeMaxDynamicSharedMemorySize, GEMM_SMEM);
    cudaFuncSetAttribute(flash_kernel, cudaFuncAttributeMaxDynamicSharedMemorySize, FLASH_SMEM);

    dim3 gblk(256);
    dim3 ggrid(HID / 128, ROWS / 128);          // (8, 128)
    dim3 wgrid(32, 32), wblk(32, 8);

    split_act<false><<<ROWS * HID / 4 / 256, 256>>>(x);

    wsplit<<<wgrid, wblk>>>(wq);
    tc_gemm<0><<<ggrid, gblk, GEMM_SMEM>>>(bq, nullptr);
    wsplit<<<wgrid, wblk>>>(wk);
    tc_gemm<1><<<ggrid, gblk, GEMM_SMEM>>>(bk, nullptr);
    wsplit<<<wgrid, wblk>>>(wv);
    tc_gemm<2><<<ggrid, gblk, GEMM_SMEM>>>(bv, nullptr);

    flash_kernel<<<dim3(SEQ / 64, NHEADS, BATCH), 256, FLASH_SMEM>>>();

    split_act<true><<<ROWS * HID / 4 / 256, 256>>>(nullptr);
    wsplit<<<wgrid, wblk>>>(wo);
    tc_gemm<3><<<ggrid, gblk, GEMM_SMEM>>>(bo, out);
}

// round 5
// speedup vs baseline: 3.1253x; 1.9006x over previous
#include <cuda_runtime.h>
#include <cuda_bf16.h>
#include <stdint.h>
#include <math.h>

// Problem constants
#define BATCH   16
#define SEQ     1024
#define HID     1024
#define NHEADS  16
#define HDIM    64
#define ROWS    (BATCH * SEQ)          // 16384
#define QKV_ELEMS (BATCH * NHEADS * SEQ * HDIM)

// ---------------------------------------------------------------------------
// Scratch (device globals: allocation is forbidden)
// ---------------------------------------------------------------------------
__device__ __nv_bfloat16 g_qh[QKV_ELEMS];   // [b][h][n][d] hi
__device__ __nv_bfloat16 g_ql[QKV_ELEMS];
__device__ __nv_bfloat16 g_kh[QKV_ELEMS];
__device__ __nv_bfloat16 g_kl[QKV_ELEMS];
__device__ __nv_bfloat16 g_vh[QKV_ELEMS];
__device__ __nv_bfloat16 g_vl[QKV_ELEMS];

__device__ __nv_bfloat16 g_ah[ROWS * HID];  // activation hi (x, then attn out)
__device__ __nv_bfloat16 g_al[ROWS * HID];  // activation lo
__device__ __nv_bfloat16 g_bh[HID * HID];   // weight^T hi  [n][k]
__device__ __nv_bfloat16 g_bl[HID * HID];   // weight^T lo  [n][k]

// ---------------------------------------------------------------------------
// PTX helpers
// ---------------------------------------------------------------------------
__device__ __forceinline__ uint32_t smem_u32(const void* p) {
    uint32_t a;
    asm("{ .reg .u64 t; cvta.to.shared.u64 t, %1; cvt.u32.u64 %0, t; }"
        : "=r"(a) : "l"(p));
    return a;
}
__device__ __forceinline__ void cp16(uint32_t dst, const void* src) {
    asm volatile("cp.async.cg.shared.global [%0], [%1], 16;" :: "r"(dst), "l"(src) : "memory");
}
#define CP_COMMIT() asm volatile("cp.async.commit_group;" ::: "memory")
#define CP_WAIT1()  asm volatile("cp.async.wait_group 1;" ::: "memory")
#define CP_WAIT0()  asm volatile("cp.async.wait_group 0;" ::: "memory")

__device__ __forceinline__ void ldsm4(uint32_t* r, uint32_t addr) {
    asm volatile("ldmatrix.sync.aligned.m8n8.x4.shared.b16 {%0,%1,%2,%3}, [%4];"
        : "=r"(r[0]), "=r"(r[1]), "=r"(r[2]), "=r"(r[3]) : "r"(addr));
}
__device__ __forceinline__ void ldsm4t(uint32_t* r, uint32_t addr) {
    asm volatile("ldmatrix.sync.aligned.m8n8.x4.trans.shared.b16 {%0,%1,%2,%3}, [%4];"
        : "=r"(r[0]), "=r"(r[1]), "=r"(r[2]), "=r"(r[3]) : "r"(addr));
}
__device__ __forceinline__ void mma16816(float* c, const uint32_t* a, const uint32_t* b) {
    asm volatile("mma.sync.aligned.m16n8k16.row.col.f32.bf16.bf16.f32 "
        "{%0,%1,%2,%3}, {%4,%5,%6,%7}, {%8,%9}, {%0,%1,%2,%3};"
        : "+f"(c[0]), "+f"(c[1]), "+f"(c[2]), "+f"(c[3])
        : "r"(a[0]), "r"(a[1]), "r"(a[2]), "r"(a[3]), "r"(b[0]), "r"(b[1]));
}

// Split (a,b) fp32 pair into packed bf16x2 hi (returned) and lo (out-param)
__device__ __forceinline__ uint32_t split2(float a, float b, uint32_t& lo) {
    __nv_bfloat162 h = __floats2bfloat162_rn(a, b);
    float ha = __bfloat162float(__low2bfloat16(h));
    float hb = __bfloat162float(__high2bfloat16(h));
    __nv_bfloat162 l = __floats2bfloat162_rn(a - ha, b - hb);
    lo = *(uint32_t*)&l;
    return *(uint32_t*)&h;
}

// ---------------------------------------------------------------------------
// Conversion kernels
// ---------------------------------------------------------------------------
__global__ __launch_bounds__(256) void split_act(const float* __restrict__ src) {
    int i = blockIdx.x * 256 + threadIdx.x;     // float4 index
    float4 a = ((const float4*)src)[i];
    uint32_t l0, l1;
    uint32_t h0 = split2(a.x, a.y, l0);
    uint32_t h1 = split2(a.z, a.w, l1);
    ((uint2*)g_ah)[i] = make_uint2(h0, h1);
    ((uint2*)g_al)[i] = make_uint2(l0, l1);
}

// W[k][n] (fp32) -> Wt_hi/lo[n][k] (bf16)
__global__ __launch_bounds__(256) void wsplit(const float* __restrict__ W) {
    __shared__ float t[32][33];
    int x0 = blockIdx.x * 32, y0 = blockIdx.y * 32;
    int tx = threadIdx.x, ty = threadIdx.y;     // block (32, 8)
#pragma unroll
    for (int j = ty; j < 32; j += 8)
        t[j][tx] = W[(size_t)(y0 + j) * HID + x0 + tx];
    __syncthreads();
#pragma unroll
    for (int j = ty; j < 32; j += 8) {
        float v = t[tx][j];                     // = W[y0+tx][x0+j]
        __nv_bfloat16 h = __float2bfloat16(v);
        __nv_bfloat16 l = __float2bfloat16(v - __bfloat162float(h));
        g_bh[(size_t)(x0 + j) * HID + y0 + tx] = h;
        g_bl[(size_t)(x0 + j) * HID + y0 + tx] = l;
    }
}

// ---------------------------------------------------------------------------
// mma.sync split-bf16 GEMM: C[16384,1024] = A @ W + bias
// MODE 0/1/2 -> emit bf16 hi/lo into g_{q,k,v}{h,l} [b,h,n,d];
// MODE 3 -> fp32 row-major OutParam.
// ---------------------------------------------------------------------------
#define SM_BIAS   64
#define SM_BUF    1024
#define STAGE_B   32768
#define GEMM_SMEM (SM_BUF + 2 * STAGE_B)
#define NSTAGES   48

__device__ __forceinline__ void load_stage(uint32_t sb, int s, int buf,
                                           int m0, int n0, int tid) {
    const int pass = s >> 4, kc = s & 15;
    const __nv_bfloat16* Ap = (pass == 1) ? g_al : g_ah;
    const __nv_bfloat16* Bp = (pass == 2) ? g_bl : g_bh;
    const int k = kc * 64;
    const uint32_t ab = sb + SM_BUF + buf * STAGE_B;
    const uint32_t bb = ab + 16384;
#pragma unroll
    for (int it = 0; it < 4; it++) {
        int c = it * 256 + tid;
        int row = c >> 3;
        int col = (c & 7) * 16;
        uint32_t off = (uint32_t)(row * 128 + col);
        uint32_t swo = off ^ ((off >> 3) & 0x70);
        cp16(ab + swo, (const char*)(Ap + (size_t)(m0 + row) * HID + k) + col);
        cp16(bb + swo, (const char*)(Bp + (size_t)(n0 + row) * HID + k) + col);
    }
}

template <int MODE>
__global__ __launch_bounds__(256, 2) void tc_gemm(const float* __restrict__ bias,
                                                  float* __restrict__ OutParam) {
    extern __shared__ char smem[];
    const uint32_t sb = smem_u32(smem);
    const int tid = threadIdx.x, wid = tid >> 5, lane = tid & 31;
    const int n0 = blockIdx.x * 128, m0 = blockIdx.y * 128;
    const int wm = wid & 1, wn = wid >> 1;
    float* sbias = (float*)(smem + SM_BIAS);

    if (tid < 128) sbias[tid] = bias[n0 + tid];

    float acc[4][4][4];
#pragma unroll
    for (int i = 0; i < 4; i++)
#pragma unroll
        for (int j = 0; j < 4; j++)
#pragma unroll
            for (int r = 0; r < 4; r++) acc[i][j][r] = 0.0f;

    const int r8 = lane & 7, midx = lane >> 3;
    const int a_row_base = wm * 64 + (midx & 1) * 8 + r8;
    const int a_c16_base = (midx >> 1);
    const int b_row_base = wn * 32 + (midx >> 1) * 8 + r8;
    const int b_c16_base = (midx & 1);

    load_stage(sb, 0, 0, m0, n0, tid);
    CP_COMMIT();

    for (int s = 0; s < NSTAGES; s++) {
        const int cur = s & 1;
        if (s + 1 < NSTAGES) {
            load_stage(sb, s + 1, cur ^ 1, m0, n0, tid);
            CP_COMMIT();
            CP_WAIT1();
        } else {
            CP_WAIT0();
        }
        __syncthreads();

        const uint32_t abase = sb + SM_BUF + cur * STAGE_B;
        const uint32_t bbase = abase + 16384;
#pragma unroll
        for (int ks = 0; ks < 4; ks++) {
            uint32_t af[4][4], bf[2][4];
#pragma unroll
            for (int i = 0; i < 4; i++) {
                int row = a_row_base + i * 16;
                int c16 = ks * 2 + a_c16_base;
                ldsm4(af[i], abase + (uint32_t)(row * 128 + ((c16 ^ (row & 7)) * 16)));
            }
#pragma unroll
            for (int jj = 0; jj < 2; jj++) {
                int row = b_row_base + jj * 16;
                int c16 = ks * 2 + b_c16_base;
                ldsm4(bf[jj], bbase + (uint32_t)(row * 128 + ((c16 ^ (row & 7)) * 16)));
            }
#pragma unroll
            for (int i = 0; i < 4; i++)
#pragma unroll
                for (int j = 0; j < 4; j++)
                    mma16816(acc[i][j], af[i], &bf[j >> 1][(j & 1) * 2]);
        }
        __syncthreads();
    }

    // Epilogue
    const int rq = lane >> 2, cq = (lane & 3) * 2;
#pragma unroll
    for (int i = 0; i < 4; i++) {
#pragma unroll
        for (int j = 0; j < 4; j++) {
            int cc = wn * 32 + j * 8 + cq;
            float b0 = sbias[cc], b1 = sbias[cc + 1];
            int mrow = m0 + wm * 64 + i * 16 + rq;
            if (MODE < 3) {
                __nv_bfloat16* oh = (MODE == 0) ? g_qh : (MODE == 1) ? g_kh : g_vh;
                __nv_bfloat16* ol = (MODE == 0) ? g_ql : (MODE == 1) ? g_kl : g_vl;
                int c_g  = n0 + cc;
                int head = c_g >> 6, d = c_g & 63;
                int b_   = mrow >> 10;
                int nn   = mrow & (SEQ - 1);
                size_t base = (((size_t)b_ * NHEADS + head) * SEQ + nn) * HDIM + d;
                uint32_t lo0, lo1;
                uint32_t hi0 = split2(acc[i][j][0] + b0, acc[i][j][1] + b1, lo0);
                uint32_t hi1 = split2(acc[i][j][2] + b0, acc[i][j][3] + b1, lo1);
                ((uint32_t*)oh)[base >> 1] = hi0;
                ((uint32_t*)ol)[base >> 1] = lo0;
                ((uint32_t*)oh)[(base + 8 * HDIM) >> 1] = hi1;
                ((uint32_t*)ol)[(base + 8 * HDIM) >> 1] = lo1;
            } else {
                float* dst = OutParam + (size_t)mrow * HID + n0 + cc;
                float2 v0 = {acc[i][j][0] + b0, acc[i][j][1] + b1};
                float2 v1 = {acc[i][j][2] + b0, acc[i][j][3] + b1};
                *(float2*)dst = v0;
                *(float2*)(dst + 8 * HID) = v1;
            }
        }
    }
}

// ---------------------------------------------------------------------------
// Tensor-core flash attention.
// CTA = (b, h, 128-query tile), 8 warps x 16 q-rows. Key tiles of 128,
// double-buffered cp.async. Split-bf16 for both QK^T and PV (3 passes each).
// Writes O directly as bf16 hi/lo into g_ah/g_al [b*n][h*64+d].
// ---------------------------------------------------------------------------
#define KV_STAGE  65536                     // Kh,Kl,Vh,Vl each 16KB
#define FLASH_SMEM (2 * KV_STAGE)
#define NKT 8                               // 1024 / 128 key tiles

__device__ __forceinline__ void load_kv(uint32_t stage, int b, int h, int kt, int tid) {
    const size_t gbase = (((size_t)b * NHEADS + h) * SEQ + kt * 128) * HDIM;
    const __nv_bfloat16* srcs[4] = {g_kh + gbase, g_kl + gbase, g_vh + gbase, g_vl + gbase};
    const int row = tid >> 3, c16 = tid & 7;
    const uint32_t swo = (uint32_t)(row * 128 + ((c16 ^ (row & 7)) << 4));
    const uint32_t goff = (uint32_t)(row * 128 + c16 * 16);
#pragma unroll
    for (int m = 0; m < 4; m++) {
        const char* src = (const char*)srcs[m];
        uint32_t base = stage + m * 16384;
#pragma unroll
        for (int it = 0; it < 4; it++)      // 32 rows per step (256 thr / 8 chunks)
            cp16(base + swo + it * 4096, src + goff + it * 4096);
    }
}

__global__ __launch_bounds__(256, 1) void flash_mma()
{
    extern __shared__ char smem[];
    const uint32_t sb = smem_u32(smem);
    const int tid = threadIdx.x, wid = tid >> 5, lane = tid & 31;
    const int b = blockIdx.z, h = blockIdx.y, q0 = blockIdx.x * 128;

    const int r8 = lane & 7, midx = lane >> 3;
    const int arow = (midx & 1) * 8 + r8;   // A-pattern rows (Q) and V-trans rows
    const int ac16 = midx >> 1;
    const int brow = (midx >> 1) * 8 + r8;  // B-pattern rows (K)
    const int bc16 = midx & 1;

    // ---- Stage Q hi/lo into smem (stage buffer 0), extract A-fragments ----
    {
        const size_t qbase = (((size_t)b * NHEADS + h) * SEQ + q0) * HDIM;
        const char* qh = (const char*)(g_qh + qbase);
        const char* ql = (const char*)(g_ql + qbase);
#pragma unroll
        for (int it = 0; it < 4; it++) {
            int c = it * 256 + tid;
            int row = c >> 3, c16 = c & 7;
            uint32_t swo = (uint32_t)(row * 128 + ((c16 ^ (row & 7)) << 4));
            cp16(sb + swo, qh + row * 128 + c16 * 16);
            cp16(sb + 16384 + swo, ql + row * 128 + c16 * 16);
        }
        CP_COMMIT(); CP_WAIT0();
    }
    __syncthreads();

    uint32_t qhf[4][4], qlf[4][4];
#pragma unroll
    for (int ks = 0; ks < 4; ks++) {
        int row = wid * 16 + arow;
        int c16 = ks * 2 + ac16;
        uint32_t swo = (uint32_t)(row * 128 + ((c16 ^ (row & 7)) << 4));
        ldsm4(qhf[ks], sb + swo);
        ldsm4(qlf[ks], sb + 16384 + swo);
    }
    __syncthreads();

    // ---- Pipeline prologue ----
    load_kv(sb, b, h, 0, tid);
    CP_COMMIT();

    float oacc[8][4];
#pragma unroll
    for (int j = 0; j < 8; j++)
#pragma unroll
        for (int r = 0; r < 4; r++) oacc[j][r] = 0.0f;
    float m0 = -1e30f, m1 = -1e30f, l0 = 0.0f, l1 = 0.0f;

    for (int kt = 0; kt < NKT; kt++) {
        const int cur = kt & 1;
        if (kt + 1 < NKT) {
            load_kv(sb + (cur ^ 1) * KV_STAGE, b, h, kt + 1, tid);
            CP_COMMIT();
            CP_WAIT1();
        } else {
            CP_WAIT0();
        }
        __syncthreads();

        const uint32_t kbh = sb + cur * KV_STAGE;
        const uint32_t kbl = kbh + 16384;
        const uint32_t vbh = kbh + 32768;
        const uint32_t vbl = kbh + 49152;

        // ---- S = Q K^T (3 split passes), fp32 accum ----
        float sacc[16][4];
#pragma unroll
        for (int t = 0; t < 16; t++)
#pragma unroll
            for (int r = 0; r < 4; r++) sacc[t][r] = 0.0f;

#pragma unroll
        for (int ks = 0; ks < 4; ks++) {
#pragma unroll
            for (int hh = 0; hh < 8; hh++) {
                uint32_t kh[4], kl[4];
                int row = hh * 16 + brow;
                int c16 = ks * 2 + bc16;
                uint32_t swo = (uint32_t)(row * 128 + ((c16 ^ (row & 7)) << 4));
                ldsm4(kh, kbh + swo);
                ldsm4(kl, kbl + swo);
                mma16816(sacc[2 * hh],     qhf[ks], kh);
                mma16816(sacc[2 * hh + 1], qhf[ks], kh + 2);
                mma16816(sacc[2 * hh],     qlf[ks], kh);
                mma16816(sacc[2 * hh + 1], qlf[ks], kh + 2);
                mma16816(sacc[2 * hh],     qhf[ks], kl);
                mma16816(sacc[2 * hh + 1], qhf[ks], kl + 2);
            }
        }

        // ---- Online softmax (rows rq = lane>>2 and rq+8) ----
        float mx0 = -1e30f, mx1 = -1e30f;
#pragma unroll
        for (int t = 0; t < 16; t++) {
            sacc[t][0] *= 0.125f; sacc[t][1] *= 0.125f;
            sacc[t][2] *= 0.125f; sacc[t][3] *= 0.125f;
            mx0 = fmaxf(mx0, fmaxf(sacc[t][0], sacc[t][1]));
            mx1 = fmaxf(mx1, fmaxf(sacc[t][2], sacc[t][3]));
        }
        mx0 = fmaxf(mx0, __shfl_xor_sync(0xffffffffu, mx0, 1));
        mx0 = fmaxf(mx0, __shfl_xor_sync(0xffffffffu, mx0, 2));
        mx1 = fmaxf(mx1, __shfl_xor_sync(0xffffffffu, mx1, 1));
        mx1 = fmaxf(mx1, __shfl_xor_sync(0xffffffffu, mx1, 2));

        float mn0 = fmaxf(m0, mx0), mn1 = fmaxf(m1, mx1);
        float al0 = __expf(m0 - mn0), al1 = __expf(m1 - mn1);
        m0 = mn0; m1 = mn1;

        float sum0 = 0.0f, sum1 = 0.0f;
#pragma unroll
        for (int t = 0; t < 16; t++) {
            sacc[t][0] = __expf(sacc[t][0] - m0); sum0 += sacc[t][0];
            sacc[t][1] = __expf(sacc[t][1] - m0); sum0 += sacc[t][1];
            sacc[t][2] = __expf(sacc[t][2] - m1); sum1 += sacc[t][2];
            sacc[t][3] = __expf(sacc[t][3] - m1); sum1 += sacc[t][3];
        }
        sum0 += __shfl_xor_sync(0xffffffffu, sum0, 1);
        sum0 += __shfl_xor_sync(0xffffffffu, sum0, 2);
        sum1 += __shfl_xor_sync(0xffffffffu, sum1, 1);
        sum1 += __shfl_xor_sync(0xffffffffu, sum1, 2);
        l0 = l0 * al0 + sum0;
        l1 = l1 * al1 + sum1;

#pragma unroll
        for (int j = 0; j < 8; j++) {
            oacc[j][0] *= al0; oacc[j][1] *= al0;
            oacc[j][2] *= al1; oacc[j][3] *= al1;
        }

        // ---- O += P V (3 split passes) ----
#pragma unroll
        for (int kk = 0; kk < 8; kk++) {
            uint32_t pah[4], pal[4];
            pah[0] = split2(sacc[2 * kk][0],     sacc[2 * kk][1],     pal[0]);
            pah[1] = split2(sacc[2 * kk][2],     sacc[2 * kk][3],     pal[1]);
            pah[2] = split2(sacc[2 * kk + 1][0], sacc[2 * kk + 1][1], pal[2]);
            pah[3] = split2(sacc[2 * kk + 1][2], sacc[2 * kk + 1][3], pal[3]);
#pragma unroll
            for (int dp = 0; dp < 4; dp++) {
                uint32_t vh[4], vl[4];
                int row = kk * 16 + arow;
                int c16 = dp * 2 + ac16;
                uint32_t swo = (uint32_t)(row * 128 + ((c16 ^ (row & 7)) << 4));
                ldsm4t(vh, vbh + swo);
                ldsm4t(vl, vbl + swo);
                mma16816(oacc[2 * dp],     pah, vh);
                mma16816(oacc[2 * dp + 1], pah, vh + 2);
                mma16816(oacc[2 * dp],     pal, vh);
                mma16816(oacc[2 * dp + 1], pal, vh + 2);
                mma16816(oacc[2 * dp],     pah, vl);
                mma16816(oacc[2 * dp + 1], pah, vl + 2);
            }
        }
        __syncthreads();
    }

    // ---- Epilogue: normalize, split hi/lo, write into activation buffers ----
    const int rq = lane >> 2, cq = lane & 3;
    float inv0 = 1.0f / l0, inv1 = 1.0f / l1;
    size_t ro0 = (size_t)(b * SEQ + q0 + wid * 16 + rq);
#pragma unroll
    for (int j = 0; j < 8; j++) {
        int col = h * 64 + j * 8 + cq * 2;
        uint32_t lo0, lo1;
        uint32_t hi0 = split2(oacc[j][0] * inv0, oacc[j][1] * inv0, lo0);
        uint32_t hi1 = split2(oacc[j][2] * inv1, oacc[j][3] * inv1, lo1);
        size_t i0 = (ro0 * HID + col) >> 1;
        size_t i1 = ((ro0 + 8) * HID + col) >> 1;
        ((uint32_t*)g_ah)[i0] = hi0;
        ((uint32_t*)g_al)[i0] = lo0;
        ((uint32_t*)g_ah)[i1] = hi1;
        ((uint32_t*)g_al)[i1] = lo1;
    }
}

// ---------------------------------------------------------------------------
extern "C" void kernel_launch(void* const* d_in, const int* in_sizes, int n_in,
                              void* d_out, int out_size)
{
    const float* x  = (const float*)d_in[0];
    const float* wq = (const float*)d_in[1];
    const float* bq = (const float*)d_in[2];
    const float* wk = (const float*)d_in[3];
    const float* bk = (const float*)d_in[4];
    const float* wv = (const float*)d_in[5];
    const float* bv = (const float*)d_in[6];
    const float* wo = (const float*)d_in[7];
    const float* bo = (const float*)d_in[8];
    float* out = (float*)d_out;

    cudaFuncSetAttribute(tc_gemm<0>, cudaFuncAttributeMaxDynamicSharedMemorySize, GEMM_SMEM);
    cudaFuncSetAttribute(tc_gemm<1>, cudaFuncAttributeMaxDynamicSharedMemorySize, GEMM_SMEM);
    cudaFuncSetAttribute(tc_gemm<2>, cudaFuncAttributeMaxDynamicSharedMemorySize, GEMM_SMEM);
    cudaFuncSetAttribute(tc_gemm<3>, cudaFuncAttributeMaxDynamicSharedMemorySize, GEMM_SMEM);
    cudaFuncSetAttribute(flash_mma,  cudaFuncAttributeMaxDynamicSharedMemorySize, FLASH_SMEM);

    dim3 gblk(256);
    dim3 ggrid(HID / 128, ROWS / 128);          // (8, 128)
    dim3 wgrid(32, 32), wblk(32, 8);

    split_act<<<ROWS * HID / 4 / 256, 256>>>(x);

    wsplit<<<wgrid, wblk>>>(wq);
    tc_gemm<0><<<ggrid, gblk, GEMM_SMEM>>>(bq, nullptr);
    wsplit<<<wgrid, wblk>>>(wk);
    tc_gemm<1><<<ggrid, gblk, GEMM_SMEM>>>(bk, nullptr);
    wsplit<<<wgrid, wblk>>>(wv);
    tc_gemm<2><<<ggrid, gblk, GEMM_SMEM>>>(bv, nullptr);

    flash_mma<<<dim3(SEQ / 128, NHEADS, BATCH), 256, FLASH_SMEM>>>();

    wsplit<<<wgrid, wblk>>>(wo);
    tc_gemm<3><<<ggrid, gblk, GEMM_SMEM>>>(bo, out);
}

// round 7
// speedup vs baseline: 3.2700x; 1.0463x over previous
#include <cuda_runtime.h>
#include <cuda_bf16.h>
#include <stdint.h>
#include <math.h>

// Problem constants
#define BATCH   16
#define SEQ     1024
#define HID     1024
#define NHEADS  16
#define HDIM    64
#define ROWS    (BATCH * SEQ)          // 16384
#define QKV_ELEMS (BATCH * NHEADS * SEQ * HDIM)

// Q is pre-scaled so that exp2(S) == softmax numerator: 0.125 * log2(e)
#define QSCALE 0.18033688011112042f

// ---------------------------------------------------------------------------
// Scratch (device globals: allocation is forbidden)
// ---------------------------------------------------------------------------
__device__ __nv_bfloat16 g_qh[QKV_ELEMS];   // [b][h][n][d] hi (pre-scaled)
__device__ __nv_bfloat16 g_ql[QKV_ELEMS];
__device__ __nv_bfloat16 g_kh[QKV_ELEMS];
__device__ __nv_bfloat16 g_kl[QKV_ELEMS];
__device__ __nv_bfloat16 g_vh[QKV_ELEMS];
__device__ __nv_bfloat16 g_vl[QKV_ELEMS];

__device__ __nv_bfloat16 g_ah[ROWS * HID];  // activation hi (x, then attn out)
__device__ __nv_bfloat16 g_al[ROWS * HID];  // activation lo
__device__ __nv_bfloat16 g_bh[HID * HID];   // weight^T hi  [n][k]
__device__ __nv_bfloat16 g_bl[HID * HID];   // weight^T lo  [n][k]

// ---------------------------------------------------------------------------
// PTX helpers
// ---------------------------------------------------------------------------
__device__ __forceinline__ uint32_t smem_u32(const void* p) {
    uint32_t a;
    asm("{ .reg .u64 t; cvta.to.shared.u64 t, %1; cvt.u32.u64 %0, t; }"
        : "=r"(a) : "l"(p));
    return a;
}
__device__ __forceinline__ void cp16(uint32_t dst, const void* src) {
    asm volatile("cp.async.cg.shared.global [%0], [%1], 16;" :: "r"(dst), "l"(src) : "memory");
}
#define CP_COMMIT() asm volatile("cp.async.commit_group;" ::: "memory")
#define CP_WAIT1()  asm volatile("cp.async.wait_group 1;" ::: "memory")
#define CP_WAIT0()  asm volatile("cp.async.wait_group 0;" ::: "memory")

__device__ __forceinline__ void ldsm4(uint32_t* r, uint32_t addr) {
    asm volatile("ldmatrix.sync.aligned.m8n8.x4.shared.b16 {%0,%1,%2,%3}, [%4];"
        : "=r"(r[0]), "=r"(r[1]), "=r"(r[2]), "=r"(r[3]) : "r"(addr));
}
__device__ __forceinline__ void ldsm4t(uint32_t* r, uint32_t addr) {
    asm volatile("ldmatrix.sync.aligned.m8n8.x4.trans.shared.b16 {%0,%1,%2,%3}, [%4];"
        : "=r"(r[0]), "=r"(r[1]), "=r"(r[2]), "=r"(r[3]) : "r"(addr));
}
__device__ __forceinline__ void mma16816(float* c, const uint32_t* a, const uint32_t* b) {
    asm volatile("mma.sync.aligned.m16n8k16.row.col.f32.bf16.bf16.f32 "
        "{%0,%1,%2,%3}, {%4,%5,%6,%7}, {%8,%9}, {%0,%1,%2,%3};"
        : "+f"(c[0]), "+f"(c[1]), "+f"(c[2]), "+f"(c[3])
        : "r"(a[0]), "r"(a[1]), "r"(a[2]), "r"(a[3]), "r"(b[0]), "r"(b[1]));
}
__device__ __forceinline__ float ex2(float x) {
    float r;
    asm("ex2.approx.ftz.f32 %0, %1;" : "=f"(r) : "f"(x));
    return r;
}

// Split (a,b) fp32 pair into packed bf16x2 hi (returned) and lo (out-param)
__device__ __forceinline__ uint32_t split2(float a, float b, uint32_t& lo) {
    __nv_bfloat162 h = __floats2bfloat162_rn(a, b);
    float ha = __bfloat162float(__low2bfloat16(h));
    float hb = __bfloat162float(__high2bfloat16(h));
    __nv_bfloat162 l = __floats2bfloat162_rn(a - ha, b - hb);
    lo = *(uint32_t*)&l;
    return *(uint32_t*)&h;
}

// ---------------------------------------------------------------------------
// Conversion kernels
// ---------------------------------------------------------------------------
__global__ __launch_bounds__(256) void split_act(const float* __restrict__ src) {
    int i = blockIdx.x * 256 + threadIdx.x;     // float4 index
    float4 a = ((const float4*)src)[i];
    uint32_t l0, l1;
    uint32_t h0 = split2(a.x, a.y, l0);
    uint32_t h1 = split2(a.z, a.w, l1);
    ((uint2*)g_ah)[i] = make_uint2(h0, h1);
    ((uint2*)g_al)[i] = make_uint2(l0, l1);
}

// W[k][n] (fp32) -> Wt_hi/lo[n][k] (bf16)
__global__ __launch_bounds__(256) void wsplit(const float* __restrict__ W) {
    __shared__ float t[32][33];
    int x0 = blockIdx.x * 32, y0 = blockIdx.y * 32;
    int tx = threadIdx.x, ty = threadIdx.y;     // block (32, 8)
#pragma unroll
    for (int j = ty; j < 32; j += 8)
        t[j][tx] = W[(size_t)(y0 + j) * HID + x0 + tx];
    __syncthreads();
#pragma unroll
    for (int j = ty; j < 32; j += 8) {
        float v = t[tx][j];                     // = W[y0+tx][x0+j]
        __nv_bfloat16 h = __float2bfloat16(v);
        __nv_bfloat16 l = __float2bfloat16(v - __bfloat162float(h));
        g_bh[(size_t)(x0 + j) * HID + y0 + tx] = h;
        g_bl[(size_t)(x0 + j) * HID + y0 + tx] = l;
    }
}

// ---------------------------------------------------------------------------
// mma.sync split-bf16 GEMM: C[16384,1024] = A @ W + bias
// 3-buffer ring, single __syncthreads per stage, depth-2 cp.async prefetch.
// MODE 0/1/2 -> emit bf16 hi/lo into g_{q,k,v}{h,l} [b,h,n,d] (Q pre-scaled);
// MODE 3 -> fp32 row-major OutParam.
// ---------------------------------------------------------------------------
#define SM_BIAS   64
#define SM_BUF    1024
#define STAGE_B   32768
#define GEMM_SMEM (SM_BUF + 3 * STAGE_B)
#define NSTAGES   48

__device__ __forceinline__ void load_stage(uint32_t sb, int s, int buf,
                                           int m0, int n0, int tid) {
    const int pass = s >> 4, kc = s & 15;
    const __nv_bfloat16* Ap = (pass == 1) ? g_al : g_ah;
    const __nv_bfloat16* Bp = (pass == 2) ? g_bl : g_bh;
    const int k = kc * 64;
    const uint32_t ab = sb + SM_BUF + buf * STAGE_B;
    const uint32_t bb = ab + 16384;
#pragma unroll
    for (int it = 0; it < 4; it++) {
        int c = it * 256 + tid;
        int row = c >> 3;
        int col = (c & 7) * 16;
        uint32_t off = (uint32_t)(row * 128 + col);
        uint32_t swo = off ^ ((off >> 3) & 0x70);
        cp16(ab + swo, (const char*)(Ap + (size_t)(m0 + row) * HID + k) + col);
        cp16(bb + swo, (const char*)(Bp + (size_t)(n0 + row) * HID + k) + col);
    }
}

template <int MODE>
__global__ __launch_bounds__(256, 2) void tc_gemm(const float* __restrict__ bias,
                                                  float* __restrict__ OutParam) {
    extern __shared__ char smem[];
    const uint32_t sb = smem_u32(smem);
    const int tid = threadIdx.x, wid = tid >> 5, lane = tid & 31;
    const int n0 = blockIdx.x * 128, m0 = blockIdx.y * 128;
    const int wm = wid & 1, wn = wid >> 1;
    float* sbias = (float*)(smem + SM_BIAS);

    if (tid < 128) sbias[tid] = bias[n0 + tid];

    float acc[4][4][4];
#pragma unroll
    for (int i = 0; i < 4; i++)
#pragma unroll
        for (int j = 0; j < 4; j++)
#pragma unroll
            for (int r = 0; r < 4; r++) acc[i][j][r] = 0.0f;

    const int r8 = lane & 7, midx = lane >> 3;
    const int a_row_base = wm * 64 + (midx & 1) * 8 + r8;
    const int a_c16_base = (midx >> 1);
    const int b_row_base = wn * 32 + (midx >> 1) * 8 + r8;
    const int b_c16_base = (midx & 1);

    // Prologue: prefetch stages 0, 1
    load_stage(sb, 0, 0, m0, n0, tid);
    CP_COMMIT();
    load_stage(sb, 1, 1, m0, n0, tid);
    CP_COMMIT();

    int mmabuf = 0, ldbuf = 2;
    for (int s = 0; s < NSTAGES; s++) {
        if (s == NSTAGES - 1) { CP_WAIT0(); } else { CP_WAIT1(); }
        __syncthreads();
        if (s + 2 < NSTAGES) {
            load_stage(sb, s + 2, ldbuf, m0, n0, tid);
            CP_COMMIT();
        }

        const uint32_t abase = sb + SM_BUF + mmabuf * STAGE_B;
        const uint32_t bbase = abase + 16384;
#pragma unroll
        for (int ks = 0; ks < 4; ks++) {
            uint32_t af[4][4], bf[2][4];
#pragma unroll
            for (int i = 0; i < 4; i++) {
                int row = a_row_base + i * 16;
                int c16 = ks * 2 + a_c16_base;
                ldsm4(af[i], abase + (uint32_t)(row * 128 + ((c16 ^ (row & 7)) * 16)));
            }
#pragma unroll
            for (int jj = 0; jj < 2; jj++) {
                int row = b_row_base + jj * 16;
                int c16 = ks * 2 + b_c16_base;
                ldsm4(bf[jj], bbase + (uint32_t)(row * 128 + ((c16 ^ (row & 7)) * 16)));
            }
#pragma unroll
            for (int i = 0; i < 4; i++)
#pragma unroll
                for (int j = 0; j < 4; j++)
                    mma16816(acc[i][j], af[i], &bf[j >> 1][(j & 1) * 2]);
        }
        mmabuf = (mmabuf == 2) ? 0 : mmabuf + 1;
        ldbuf  = (ldbuf  == 2) ? 0 : ldbuf  + 1;
    }

    // Epilogue
    const int rq = lane >> 2, cq = (lane & 3) * 2;
#pragma unroll
    for (int i = 0; i < 4; i++) {
#pragma unroll
        for (int j = 0; j < 4; j++) {
            int cc = wn * 32 + j * 8 + cq;
            float b0 = sbias[cc], b1 = sbias[cc + 1];
            int mrow = m0 + wm * 64 + i * 16 + rq;
            if (MODE < 3) {
                __nv_bfloat16* oh = (MODE == 0) ? g_qh : (MODE == 1) ? g_kh : g_vh;
                __nv_bfloat16* ol = (MODE == 0) ? g_ql : (MODE == 1) ? g_kl : g_vl;
                const float scl = (MODE == 0) ? QSCALE : 1.0f;
                int c_g  = n0 + cc;
                int head = c_g >> 6, d = c_g & 63;
                int b_   = mrow >> 10;
                int nn   = mrow & (SEQ - 1);
                size_t base = (((size_t)b_ * NHEADS + head) * SEQ + nn) * HDIM + d;
                uint32_t lo0, lo1;
                uint32_t hi0 = split2((acc[i][j][0] + b0) * scl, (acc[i][j][1] + b1) * scl, lo0);
                uint32_t hi1 = split2((acc[i][j][2] + b0) * scl, (acc[i][j][3] + b1) * scl, lo1);
                ((uint32_t*)oh)[base >> 1] = hi0;
                ((uint32_t*)ol)[base >> 1] = lo0;
                ((uint32_t*)oh)[(base + 8 * HDIM) >> 1] = hi1;
                ((uint32_t*)ol)[(base + 8 * HDIM) >> 1] = lo1;
            } else {
                float* dst = OutParam + (size_t)mrow * HID + n0 + cc;
                float2 v0 = {acc[i][j][0] + b0, acc[i][j][1] + b1};
                float2 v1 = {acc[i][j][2] + b0, acc[i][j][3] + b1};
                *(float2*)dst = v0;
                *(float2*)(dst + 8 * HID) = v1;
            }
        }
    }
}

// ---------------------------------------------------------------------------
// Tensor-core flash attention, key tile 64, no-max softmax (Q pre-scaled so
// p = exp2(S) is the softmax numerator; scores are O(1), no overflow risk).
// CTA = (b, h, 128-query tile), 8 warps x 16 q-rows, 64 KB smem, 2 CTAs/SM.
// Writes O directly as bf16 hi/lo into g_ah/g_al [b*n][h*64+d].
// ---------------------------------------------------------------------------
#define KV_STAGE  32768                     // Kh,Kl,Vh,Vl each 8KB (64x128B)
#define FLASH_SMEM (2 * KV_STAGE)
#define NKT 16                              // 1024 / 64 key tiles

__device__ __forceinline__ void load_kv(uint32_t stage, int b, int h, int kt, int tid) {
    const size_t gbase = (((size_t)b * NHEADS + h) * SEQ + kt * 64) * HDIM;
    const __nv_bfloat16* srcs[4] = {g_kh + gbase, g_kl + gbase, g_vh + gbase, g_vl + gbase};
    const int row = tid >> 3, c16 = tid & 7;
    const uint32_t swo = (uint32_t)(row * 128 + ((c16 ^ (row & 7)) << 4));
    const uint32_t goff = (uint32_t)(row * 128 + c16 * 16);
#pragma unroll
    for (int m = 0; m < 4; m++) {
        const char* src = (const char*)srcs[m];
        uint32_t base = stage + m * 8192;
        cp16(base + swo, src + goff);                   // rows 0..31
        cp16(base + swo + 4096, src + goff + 4096);     // rows 32..63
    }
}

__global__ __launch_bounds__(256, 2) void flash_mma()
{
    extern __shared__ char smem[];
    const uint32_t sb = smem_u32(smem);
    const int tid = threadIdx.x, wid = tid >> 5, lane = tid & 31;
    const int b = blockIdx.z, h = blockIdx.y, q0 = blockIdx.x * 128;

    const int r8 = lane & 7, midx = lane >> 3;
    const int arow = (midx & 1) * 8 + r8;   // A-pattern rows (Q) and V-trans rows
    const int ac16 = midx >> 1;
    const int brow = (midx >> 1) * 8 + r8;  // B-pattern rows (K)
    const int bc16 = midx & 1;

    // ---- Stage Q hi/lo into smem (overlaid on stage buffer 0) ----
    {
        const size_t qbase = (((size_t)b * NHEADS + h) * SEQ + q0) * HDIM;
        const char* qh = (const char*)(g_qh + qbase);
        const char* ql = (const char*)(g_ql + qbase);
#pragma unroll
        for (int it = 0; it < 4; it++) {
            int c = it * 256 + tid;
            int row = c >> 3, c16 = c & 7;
            uint32_t swo = (uint32_t)(row * 128 + ((c16 ^ (row & 7)) << 4));
            cp16(sb + swo, qh + row * 128 + c16 * 16);
            cp16(sb + 16384 + swo, ql + row * 128 + c16 * 16);
        }
        CP_COMMIT(); CP_WAIT0();
    }
    __syncthreads();

    uint32_t qhf[4][4], qlf[4][4];
#pragma unroll
    for (int ks = 0; ks < 4; ks++) {
        int row = wid * 16 + arow;
        int c16 = ks * 2 + ac16;
        uint32_t swo = (uint32_t)(row * 128 + ((c16 ^ (row & 7)) << 4));
        ldsm4(qhf[ks], sb + swo);
        ldsm4(qlf[ks], sb + 16384 + swo);
    }
    __syncthreads();

    // ---- Pipeline prologue ----
    load_kv(sb, b, h, 0, tid);
    CP_COMMIT();

    float oacc[8][4];
#pragma unroll
    for (int j = 0; j < 8; j++)
#pragma unroll
        for (int r = 0; r < 4; r++) oacc[j][r] = 0.0f;
    float l0 = 0.0f, l1 = 0.0f;

    for (int kt = 0; kt < NKT; kt++) {
        const int cur = kt & 1;
        if (kt + 1 < NKT) {
            load_kv(sb + (cur ^ 1) * KV_STAGE, b, h, kt + 1, tid);
            CP_COMMIT();
            CP_WAIT1();
        } else {
            CP_WAIT0();
        }
        __syncthreads();

        const uint32_t kbh = sb + cur * KV_STAGE;
        const uint32_t kbl = kbh + 8192;
        const uint32_t vbh = kbh + 16384;
        const uint32_t vbl = kbh + 24576;

        // ---- S = Q K^T (3 split passes), fp32 accum ----
        float sacc[8][4];
#pragma unroll
        for (int t = 0; t < 8; t++)
#pragma unroll
            for (int r = 0; r < 4; r++) sacc[t][r] = 0.0f;

#pragma unroll
        for (int ks = 0; ks < 4; ks++) {
#pragma unroll
            for (int hh = 0; hh < 4; hh++) {
                uint32_t kh[4], kl[4];
                int row = hh * 16 + brow;
                int c16 = ks * 2 + bc16;
                uint32_t swo = (uint32_t)(row * 128 + ((c16 ^ (row & 7)) << 4));
                ldsm4(kh, kbh + swo);
                ldsm4(kl, kbl + swo);
                mma16816(sacc[2 * hh],     qhf[ks], kh);
                mma16816(sacc[2 * hh + 1], qhf[ks], kh + 2);
                mma16816(sacc[2 * hh],     qlf[ks], kh);
                mma16816(sacc[2 * hh + 1], qlf[ks], kh + 2);
                mma16816(sacc[2 * hh],     qhf[ks], kl);
                mma16816(sacc[2 * hh + 1], qhf[ks], kl + 2);
            }
        }

        // ---- p = exp2(S); accumulate row sums locally (no shfl here) ----
#pragma unroll
        for (int t = 0; t < 8; t++) {
            sacc[t][0] = ex2(sacc[t][0]);
            sacc[t][1] = ex2(sacc[t][1]);
            sacc[t][2] = ex2(sacc[t][2]);
            sacc[t][3] = ex2(sacc[t][3]);
            l0 += sacc[t][0] + sacc[t][1];
            l1 += sacc[t][2] + sacc[t][3];
        }

        // ---- O += P V (3 split passes) ----
#pragma unroll
        for (int kk = 0; kk < 4; kk++) {
            uint32_t pah[4], pal[4];
            pah[0] = split2(sacc[2 * kk][0],     sacc[2 * kk][1],     pal[0]);
            pah[1] = split2(sacc[2 * kk][2],     sacc[2 * kk][3],     pal[1]);
            pah[2] = split2(sacc[2 * kk + 1][0], sacc[2 * kk + 1][1], pal[2]);
            pah[3] = split2(sacc[2 * kk + 1][2], sacc[2 * kk + 1][3], pal[3]);
#pragma unroll
            for (int dp = 0; dp < 4; dp++) {
                uint32_t vh[4], vl[4];
                int row = kk * 16 + arow;
                int c16 = dp * 2 + ac16;
                uint32_t swo = (uint32_t)(row * 128 + ((c16 ^ (row & 7)) << 4));
                ldsm4t(vh, vbh + swo);
                ldsm4t(vl, vbl + swo);
                mma16816(oacc[2 * dp],     pah, vh);
                mma16816(oacc[2 * dp + 1], pah, vh + 2);
                mma16816(oacc[2 * dp],     pal, vh);
                mma16816(oacc[2 * dp + 1], pal, vh + 2);
                mma16816(oacc[2 * dp],     pah, vl);
                mma16816(oacc[2 * dp + 1], pah, vl + 2);
            }
        }
        __syncthreads();
    }

    // ---- Epilogue: reduce l across the 4 lanes of each row, normalize ----
    l0 += __shfl_xor_sync(0xffffffffu, l0, 1);
    l0 += __shfl_xor_sync(0xffffffffu, l0, 2);
    l1 += __shfl_xor_sync(0xffffffffu, l1, 1);
    l1 += __shfl_xor_sync(0xffffffffu, l1, 2);

    const int rq = lane >> 2, cq = lane & 3;
    float inv0 = 1.0f / l0, inv1 = 1.0f / l1;
    size_t ro0 = (size_t)(b * SEQ + q0 + wid * 16 + rq);
#pragma unroll
    for (int j = 0; j < 8; j++) {
        int col = h * 64 + j * 8 + cq * 2;
        uint32_t lo0, lo1;
        uint32_t hi0 = split2(oacc[j][0] * inv0, oacc[j][1] * inv0, lo0);
        uint32_t hi1 = split2(oacc[j][2] * inv1, oacc[j][3] * inv1, lo1);
        size_t i0 = (ro0 * HID + col) >> 1;
        size_t i1 = ((ro0 + 8) * HID + col) >> 1;
        ((uint32_t*)g_ah)[i0] = hi0;
        ((uint32_t*)g_al)[i0] = lo0;
        ((uint32_t*)g_ah)[i1] = hi1;
        ((uint32_t*)g_al)[i1] = lo1;
    }
}

// ---------------------------------------------------------------------------
extern "C" void kernel_launch(void* const* d_in, const int* in_sizes, int n_in,
                              void* d_out, int out_size)
{
    const float* x  = (const float*)d_in[0];
    const float* wq = (const float*)d_in[1];
    const float* bq = (const float*)d_in[2];
    const float* wk = (const float*)d_in[3];
    const float* bk = (const float*)d_in[4];
    const float* wv = (const float*)d_in[5];
    const float* bv = (const float*)d_in[6];
    const float* wo = (const float*)d_in[7];
    const float* bo = (const float*)d_in[8];
    float* out = (float*)d_out;

    cudaFuncSetAttribute(tc_gemm<0>, cudaFuncAttributeMaxDynamicSharedMemorySize, GEMM_SMEM);
    cudaFuncSetAttribute(tc_gemm<1>, cudaFuncAttributeMaxDynamicSharedMemorySize, GEMM_SMEM);
    cudaFuncSetAttribute(tc_gemm<2>, cudaFuncAttributeMaxDynamicSharedMemorySize, GEMM_SMEM);
    cudaFuncSetAttribute(tc_gemm<3>, cudaFuncAttributeMaxDynamicSharedMemorySize, GEMM_SMEM);
    cudaFuncSetAttribute(flash_mma,  cudaFuncAttributeMaxDynamicSharedMemorySize, FLASH_SMEM);

    dim3 gblk(256);
    dim3 ggrid(HID / 128, ROWS / 128);          // (8, 128)
    dim3 wgrid(32, 32), wblk(32, 8);

    split_act<<<ROWS * HID / 4 / 256, 256>>>(x);

    wsplit<<<wgrid, wblk>>>(wq);
    tc_gemm<0><<<ggrid, gblk, GEMM_SMEM>>>(bq, nullptr);
    wsplit<<<wgrid, wblk>>>(wk);
    tc_gemm<1><<<ggrid, gblk, GEMM_SMEM>>>(bk, nullptr);
    wsplit<<<wgrid, wblk>>>(wv);
    tc_gemm<2><<<ggrid, gblk, GEMM_SMEM>>>(bv, nullptr);

    flash_mma<<<dim3(SEQ / 128, NHEADS, BATCH), 256, FLASH_SMEM>>>();

    wsplit<<<wgrid, wblk>>>(wo);
    tc_gemm<3><<<ggrid, gblk, GEMM_SMEM>>>(bo, out);
}

// round 9
// speedup vs baseline: 4.9944x; 1.5274x over previous
#include <cuda_runtime.h>
#include <cuda_fp16.h>
#include <stdint.h>
#include <math.h>

// Problem constants
#define BATCH   16
#define SEQ     1024
#define HID     1024
#define NHEADS  16
#define HDIM    64
#define ROWS    (BATCH * SEQ)          // 16384
#define QKV_ELEMS (BATCH * NHEADS * SEQ * HDIM)

// Q is pre-scaled so that exp2(S) == softmax numerator: 0.125 * log2(e)
#define QSCALE 0.18033688011112042f

// ---------------------------------------------------------------------------
// Scratch (device globals: allocation is forbidden)
// ---------------------------------------------------------------------------
__device__ __half g_qh[QKV_ELEMS];          // [b][h][n][d] hi (pre-scaled)
__device__ __half g_ql[QKV_ELEMS];          // lo
__device__ __half g_kh[QKV_ELEMS];          // hi only
__device__ __half g_vh[QKV_ELEMS];          // hi only

__device__ __half g_ah[ROWS * HID];         // activation hi (x, then attn out)
__device__ __half g_al[ROWS * HID];         // activation lo
__device__ __half g_wh[4][HID * HID];       // weight^T hi [n][k] (q,k,v,o)

// ---------------------------------------------------------------------------
// PTX helpers
// ---------------------------------------------------------------------------
__device__ __forceinline__ uint32_t smem_u32(const void* p) {
    uint32_t a;
    asm("{ .reg .u64 t; cvta.to.shared.u64 t, %1; cvt.u32.u64 %0, t; }"
        : "=r"(a) : "l"(p));
    return a;
}
__device__ __forceinline__ void cp16(uint32_t dst, const void* src) {
    asm volatile("cp.async.cg.shared.global [%0], [%1], 16;" :: "r"(dst), "l"(src) : "memory");
}
#define CP_COMMIT() asm volatile("cp.async.commit_group;" ::: "memory")
#define CP_WAIT1()  asm volatile("cp.async.wait_group 1;" ::: "memory")
#define CP_WAIT0()  asm volatile("cp.async.wait_group 0;" ::: "memory")

__device__ __forceinline__ void ldsm4(uint32_t* r, uint32_t addr) {
    asm volatile("ldmatrix.sync.aligned.m8n8.x4.shared.b16 {%0,%1,%2,%3}, [%4];"
        : "=r"(r[0]), "=r"(r[1]), "=r"(r[2]), "=r"(r[3]) : "r"(addr));
}
__device__ __forceinline__ void ldsm4t(uint32_t* r, uint32_t addr) {
    asm volatile("ldmatrix.sync.aligned.m8n8.x4.trans.shared.b16 {%0,%1,%2,%3}, [%4];"
        : "=r"(r[0]), "=r"(r[1]), "=r"(r[2]), "=r"(r[3]) : "r"(addr));
}
__device__ __forceinline__ void mma16816(float* c, const uint32_t* a, const uint32_t* b) {
    asm volatile("mma.sync.aligned.m16n8k16.row.col.f32.f16.f16.f32 "
        "{%0,%1,%2,%3}, {%4,%5,%6,%7}, {%8,%9}, {%0,%1,%2,%3};"
        : "+f"(c[0]), "+f"(c[1]), "+f"(c[2]), "+f"(c[3])
        : "r"(a[0]), "r"(a[1]), "r"(a[2]), "r"(a[3]), "r"(b[0]), "r"(b[1]));
}
__device__ __forceinline__ float ex2(float x) {
    float r;
    asm("ex2.approx.ftz.f32 %0, %1;" : "=f"(r) : "f"(x));
    return r;
}

// Split (a,b) fp32 pair into packed fp16x2 hi (returned) and lo (out-param)
__device__ __forceinline__ uint32_t split2h(float a, float b, uint32_t& lo) {
    __half2 h = __floats2half2_rn(a, b);
    float ha = __low2float(h), hb = __high2float(h);
    __half2 l = __floats2half2_rn(a - ha, b - hb);
    lo = *(uint32_t*)&l;
    return *(uint32_t*)&h;
}
__device__ __forceinline__ uint32_t pack2h(float a, float b) {
    __half2 h = __floats2half2_rn(a, b);
    return *(uint32_t*)&h;
}

// ---------------------------------------------------------------------------
// Conversion kernels
// ---------------------------------------------------------------------------
__global__ __launch_bounds__(256) void split_act(const float* __restrict__ src) {
    int i = blockIdx.x * 256 + threadIdx.x;     // float4 index
    float4 a = ((const float4*)src)[i];
    uint32_t l0, l1;
    uint32_t h0 = split2h(a.x, a.y, l0);
    uint32_t h1 = split2h(a.z, a.w, l1);
    ((uint2*)g_ah)[i] = make_uint2(h0, h1);
    ((uint2*)g_al)[i] = make_uint2(l0, l1);
}

// All four W[k][n] (fp32) -> Wt_hi[n][k] (fp16), one launch
__global__ __launch_bounds__(256) void wsplit_all(const float* __restrict__ wq,
                                                  const float* __restrict__ wk,
                                                  const float* __restrict__ wv,
                                                  const float* __restrict__ wo) {
    __shared__ float t[32][33];
    const float* W = (blockIdx.z == 0) ? wq : (blockIdx.z == 1) ? wk
                   : (blockIdx.z == 2) ? wv : wo;
    __half* dst = g_wh[blockIdx.z];
    int x0 = blockIdx.x * 32, y0 = blockIdx.y * 32;
    int tx = threadIdx.x, ty = threadIdx.y;     // block (32, 8)
#pragma unroll
    for (int j = ty; j < 32; j += 8)
        t[j][tx] = W[(size_t)(y0 + j) * HID + x0 + tx];
    __syncthreads();
#pragma unroll
    for (int j = ty; j < 32; j += 8)
        dst[(size_t)(x0 + j) * HID + y0 + tx] = __float2half_rn(t[tx][j]);
}

// ---------------------------------------------------------------------------
// mma.sync split-fp16 GEMM: C[16384,1024] = (Ah+Al) @ Wh + bias  (2 passes)
// 16 K-stages of 64; each stage holds Ah(16K)+Al(16K)+Bh(16K); 2-buffer ring.
// MODE 0 -> Q hi/lo (pre-scaled); MODE 1/2 -> K/V hi only; MODE 3 -> fp32 out.
// ---------------------------------------------------------------------------
#define SM_BIAS   64
#define SM_BUF    1024
#define STAGE_B   49152
#define GEMM_SMEM (SM_BUF + 2 * STAGE_B)
#define NSTAGES   16

template <int MODE>
__device__ __forceinline__ void load_stage(uint32_t sb, int kc, int buf,
                                           int m0, int n0, int tid) {
    const int k = kc * 64;
    const uint32_t base = sb + SM_BUF + buf * STAGE_B;
    const __half* Bp = g_wh[MODE];
#pragma unroll
    for (int it = 0; it < 4; it++) {
        int c = it * 256 + tid;
        int row = c >> 3;
        int col = (c & 7) * 16;
        uint32_t off = (uint32_t)(row * 128 + col);
        uint32_t swo = off ^ ((off >> 3) & 0x70);
        cp16(base + swo,         (const char*)(g_ah + (size_t)(m0 + row) * HID + k) + col);
        cp16(base + 16384 + swo, (const char*)(g_al + (size_t)(m0 + row) * HID + k) + col);
        cp16(base + 32768 + swo, (const char*)(Bp   + (size_t)(n0 + row) * HID + k) + col);
    }
}

template <int MODE>
__global__ __launch_bounds__(256, 2) void tc_gemm(const float* __restrict__ bias,
                                                  float* __restrict__ OutParam) {
    extern __shared__ char smem[];
    const uint32_t sb = smem_u32(smem);
    const int tid = threadIdx.x, wid = tid >> 5, lane = tid & 31;
    const int n0 = blockIdx.x * 128, m0 = blockIdx.y * 128;
    const int wm = wid & 1, wn = wid >> 1;
    float* sbias = (float*)(smem + SM_BIAS);

    if (tid < 128) sbias[tid] = bias[n0 + tid];

    float acc[4][4][4];
#pragma unroll
    for (int i = 0; i < 4; i++)
#pragma unroll
        for (int j = 0; j < 4; j++)
#pragma unroll
            for (int r = 0; r < 4; r++) acc[i][j][r] = 0.0f;

    const int r8 = lane & 7, midx = lane >> 3;
    const int a_row_base = wm * 64 + (midx & 1) * 8 + r8;
    const int a_c16_base = (midx >> 1);
    const int b_row_base = wn * 32 + (midx >> 1) * 8 + r8;
    const int b_c16_base = (midx & 1);

    // Prologue: stage 0
    load_stage<MODE>(sb, 0, 0, m0, n0, tid);
    CP_COMMIT();

    for (int s = 0; s < NSTAGES; s++) {
        if (s + 1 < NSTAGES) {
            load_stage<MODE>(sb, s + 1, (s + 1) & 1, m0, n0, tid);
            CP_COMMIT();
            CP_WAIT1();
        } else {
            CP_WAIT0();
        }
        __syncthreads();

        const uint32_t abase = sb + SM_BUF + (s & 1) * STAGE_B;
        const uint32_t lbase = abase + 16384;
        const uint32_t bbase = abase + 32768;
#pragma unroll
        for (int ks = 0; ks < 4; ks++) {
            uint32_t afh[4][4], afl[4][4], bf[2][4];
#pragma unroll
            for (int i = 0; i < 4; i++) {
                int row = a_row_base + i * 16;
                int c16 = ks * 2 + a_c16_base;
                uint32_t swo = (uint32_t)(row * 128 + ((c16 ^ (row & 7)) * 16));
                ldsm4(afh[i], abase + swo);
                ldsm4(afl[i], lbase + swo);
            }
#pragma unroll
            for (int jj = 0; jj < 2; jj++) {
                int row = b_row_base + jj * 16;
                int c16 = ks * 2 + b_c16_base;
                ldsm4(bf[jj], bbase + (uint32_t)(row * 128 + ((c16 ^ (row & 7)) * 16)));
            }
#pragma unroll
            for (int i = 0; i < 4; i++)
#pragma unroll
                for (int j = 0; j < 4; j++) {
                    mma16816(acc[i][j], afh[i], &bf[j >> 1][(j & 1) * 2]);
                    mma16816(acc[i][j], afl[i], &bf[j >> 1][(j & 1) * 2]);
                }
        }
        __syncthreads();
    }

    // Epilogue
    const int rq = lane >> 2, cq = (lane & 3) * 2;
#pragma unroll
    for (int i = 0; i < 4; i++) {
#pragma unroll
        for (int j = 0; j < 4; j++) {
            int cc = wn * 32 + j * 8 + cq;
            float b0 = sbias[cc], b1 = sbias[cc + 1];
            int mrow = m0 + wm * 64 + i * 16 + rq;
            if (MODE < 3) {
                int c_g  = n0 + cc;
                int head = c_g >> 6, d = c_g & 63;
                int b_   = mrow >> 10;
                int nn   = mrow & (SEQ - 1);
                size_t base = (((size_t)b_ * NHEADS + head) * SEQ + nn) * HDIM + d;
                if (MODE == 0) {
                    uint32_t lo0, lo1;
                    uint32_t hi0 = split2h((acc[i][j][0] + b0) * QSCALE,
                                           (acc[i][j][1] + b1) * QSCALE, lo0);
                    uint32_t hi1 = split2h((acc[i][j][2] + b0) * QSCALE,
                                           (acc[i][j][3] + b1) * QSCALE, lo1);
                    ((uint32_t*)g_qh)[base >> 1] = hi0;
                    ((uint32_t*)g_ql)[base >> 1] = lo0;
                    ((uint32_t*)g_qh)[(base + 8 * HDIM) >> 1] = hi1;
                    ((uint32_t*)g_ql)[(base + 8 * HDIM) >> 1] = lo1;
                } else {
                    __half* oh = (MODE == 1) ? g_kh : g_vh;
                    ((uint32_t*)oh)[base >> 1] =
                        pack2h(acc[i][j][0] + b0, acc[i][j][1] + b1);
                    ((uint32_t*)oh)[(base + 8 * HDIM) >> 1] =
                        pack2h(acc[i][j][2] + b0, acc[i][j][3] + b1);
                }
            } else {
                float* dst = OutParam + (size_t)mrow * HID + n0 + cc;
                float2 v0 = {acc[i][j][0] + b0, acc[i][j][1] + b1};
                float2 v1 = {acc[i][j][2] + b0, acc[i][j][3] + b1};
                *(float2*)dst = v0;
                *(float2*)(dst + 8 * HID) = v1;
            }
        }
    }
}

// ---------------------------------------------------------------------------
// Tensor-core flash attention, fp16 2-pass, key tile 64, no-max softmax.
// S = (Qh+Ql)Kh ; O += (Ph+Pl)Vh.  CTA = (b,h,128 queries), 8 warps, 32KB smem.
// ---------------------------------------------------------------------------
#define KV_STAGE  16384                     // Kh 8KB + Vh 8KB
#define FLASH_SMEM (2 * KV_STAGE)
#define NKT 16                              // 1024 / 64 key tiles

__device__ __forceinline__ void load_kv(uint32_t stage, int b, int h, int kt, int tid) {
    const size_t gbase = (((size_t)b * NHEADS + h) * SEQ + kt * 64) * HDIM;
    const int row = tid >> 3, c16 = tid & 7;
    const uint32_t swo = (uint32_t)(row * 128 + ((c16 ^ (row & 7)) << 4));
    const uint32_t goff = (uint32_t)(row * 128 + c16 * 16);
    const char* ksrc = (const char*)(g_kh + gbase);
    const char* vsrc = (const char*)(g_vh + gbase);
    cp16(stage + swo,         ksrc + goff);             // K rows 0..31
    cp16(stage + swo + 4096,  ksrc + goff + 4096);      // K rows 32..63
    cp16(stage + 8192 + swo,        vsrc + goff);       // V rows 0..31
    cp16(stage + 8192 + swo + 4096, vsrc + goff + 4096);// V rows 32..63
}

__global__ __launch_bounds__(256, 2) void flash_mma()
{
    extern __shared__ char smem[];
    const uint32_t sb = smem_u32(smem);
    const int tid = threadIdx.x, wid = tid >> 5, lane = tid & 31;
    const int b = blockIdx.z, h = blockIdx.y, q0 = blockIdx.x * 128;

    const int r8 = lane & 7, midx = lane >> 3;
    const int arow = (midx & 1) * 8 + r8;   // A-pattern rows (Q) and V-trans rows
    const int ac16 = midx >> 1;
    const int brow = (midx >> 1) * 8 + r8;  // B-pattern rows (K)
    const int bc16 = midx & 1;

    // ---- Stage Q hi/lo into smem (overlaid on both stage buffers) ----
    {
        const size_t qbase = (((size_t)b * NHEADS + h) * SEQ + q0) * HDIM;
        const char* qh = (const char*)(g_qh + qbase);
        const char* ql = (const char*)(g_ql + qbase);
#pragma unroll
        for (int it = 0; it < 4; it++) {
            int c = it * 256 + tid;
            int row = c >> 3, c16 = c & 7;
            uint32_t swo = (uint32_t)(row * 128 + ((c16 ^ (row & 7)) << 4));
            cp16(sb + swo, qh + row * 128 + c16 * 16);
            cp16(sb + 16384 + swo, ql + row * 128 + c16 * 16);
        }
        CP_COMMIT(); CP_WAIT0();
    }
    __syncthreads();

    uint32_t qhf[4][4], qlf[4][4];
#pragma unroll
    for (int ks = 0; ks < 4; ks++) {
        int row = wid * 16 + arow;
        int c16 = ks * 2 + ac16;
        uint32_t swo = (uint32_t)(row * 128 + ((c16 ^ (row & 7)) << 4));
        ldsm4(qhf[ks], sb + swo);
        ldsm4(qlf[ks], sb + 16384 + swo);
    }
    __syncthreads();

    // ---- Pipeline prologue ----
    load_kv(sb, b, h, 0, tid);
    CP_COMMIT();

    float oacc[8][4];
#pragma unroll
    for (int j = 0; j < 8; j++)
#pragma unroll
        for (int r = 0; r < 4; r++) oacc[j][r] = 0.0f;
    float l0 = 0.0f, l1 = 0.0f;

    for (int kt = 0; kt < NKT; kt++) {
        const int cur = kt & 1;
        if (kt + 1 < NKT) {
            load_kv(sb + (cur ^ 1) * KV_STAGE, b, h, kt + 1, tid);
            CP_COMMIT();
            CP_WAIT1();
        } else {
            CP_WAIT0();
        }
        __syncthreads();

        const uint32_t kbh = sb + cur * KV_STAGE;
        const uint32_t vbh = kbh + 8192;

        // ---- S = (Qh+Ql) Kh, fp32 accum ----
        float sacc[8][4];
#pragma unroll
        for (int t = 0; t < 8; t++)
#pragma unroll
            for (int r = 0; r < 4; r++) sacc[t][r] = 0.0f;

#pragma unroll
        for (int ks = 0; ks < 4; ks++) {
#pragma unroll
            for (int hh = 0; hh < 4; hh++) {
                uint32_t kh[4];
                int row = hh * 16 + brow;
                int c16 = ks * 2 + bc16;
                uint32_t swo = (uint32_t)(row * 128 + ((c16 ^ (row & 7)) << 4));
                ldsm4(kh, kbh + swo);
                mma16816(sacc[2 * hh],     qhf[ks], kh);
                mma16816(sacc[2 * hh + 1], qhf[ks], kh + 2);
                mma16816(sacc[2 * hh],     qlf[ks], kh);
                mma16816(sacc[2 * hh + 1], qlf[ks], kh + 2);
            }
        }

        // ---- p = exp2(S); accumulate row sums locally ----
#pragma unroll
        for (int t = 0; t < 8; t++) {
            sacc[t][0] = ex2(sacc[t][0]);
            sacc[t][1] = ex2(sacc[t][1]);
            sacc[t][2] = ex2(sacc[t][2]);
            sacc[t][3] = ex2(sacc[t][3]);
            l0 += sacc[t][0] + sacc[t][1];
            l1 += sacc[t][2] + sacc[t][3];
        }

        // ---- O += (Ph+Pl) Vh ----
#pragma unroll
        for (int kk = 0; kk < 4; kk++) {
            uint32_t pah[4], pal[4];
            pah[0] = split2h(sacc[2 * kk][0],     sacc[2 * kk][1],     pal[0]);
            pah[1] = split2h(sacc[2 * kk][2],     sacc[2 * kk][3],     pal[1]);
            pah[2] = split2h(sacc[2 * kk + 1][0], sacc[2 * kk + 1][1], pal[2]);
            pah[3] = split2h(sacc[2 * kk + 1][2], sacc[2 * kk + 1][3], pal[3]);
#pragma unroll
            for (int dp = 0; dp < 4; dp++) {
                uint32_t vh[4];
                int row = kk * 16 + arow;
                int c16 = dp * 2 + ac16;
                uint32_t swo = (uint32_t)(row * 128 + ((c16 ^ (row & 7)) << 4));
                ldsm4t(vh, vbh + swo);
                mma16816(oacc[2 * dp],     pah, vh);
                mma16816(oacc[2 * dp + 1], pah, vh + 2);
                mma16816(oacc[2 * dp],     pal, vh);
                mma16816(oacc[2 * dp + 1], pal, vh + 2);
            }
        }
        __syncthreads();
    }

    // ---- Epilogue: reduce l across the 4 lanes of each row, normalize ----
    l0 += __shfl_xor_sync(0xffffffffu, l0, 1);
    l0 += __shfl_xor_sync(0xffffffffu, l0, 2);
    l1 += __shfl_xor_sync(0xffffffffu, l1, 1);
    l1 += __shfl_xor_sync(0xffffffffu, l1, 2);

    const int rq = lane >> 2, cq = lane & 3;
    float inv0 = 1.0f / l0, inv1 = 1.0f / l1;
    size_t ro0 = (size_t)(b * SEQ + q0 + wid * 16 + rq);
#pragma unroll
    for (int j = 0; j < 8; j++) {
        int col = h * 64 + j * 8 + cq * 2;
        uint32_t lo0, lo1;
        uint32_t hi0 = split2h(oacc[j][0] * inv0, oacc[j][1] * inv0, lo0);
        uint32_t hi1 = split2h(oacc[j][2] * inv1, oacc[j][3] * inv1, lo1);
        size_t i0 = (ro0 * HID + col) >> 1;
        size_t i1 = ((ro0 + 8) * HID + col) >> 1;
        ((uint32_t*)g_ah)[i0] = hi0;
        ((uint32_t*)g_al)[i0] = lo0;
        ((uint32_t*)g_ah)[i1] = hi1;
        ((uint32_t*)g_al)[i1] = lo1;
    }
}

// ---------------------------------------------------------------------------
extern "C" void kernel_launch(void* const* d_in, const int* in_sizes, int n_in,
                              void* d_out, int out_size)
{
    const float* x  = (const float*)d_in[0];
    const float* wq = (const float*)d_in[1];
    const float* bq = (const float*)d_in[2];
    const float* wk = (const float*)d_in[3];
    const float* bk = (const float*)d_in[4];
    const float* wv = (const float*)d_in[5];
    const float* bv = (const float*)d_in[6];
    const float* wo = (const float*)d_in[7];
    const float* bo = (const float*)d_in[8];
    float* out = (float*)d_out;

    cudaFuncSetAttribute(tc_gemm<0>, cudaFuncAttributeMaxDynamicSharedMemorySize, GEMM_SMEM);
    cudaFuncSetAttribute(tc_gemm<1>, cudaFuncAttributeMaxDynamicSharedMemorySize, GEMM_SMEM);
    cudaFuncSetAttribute(tc_gemm<2>, cudaFuncAttributeMaxDynamicSharedMemorySize, GEMM_SMEM);
    cudaFuncSetAttribute(tc_gemm<3>, cudaFuncAttributeMaxDynamicSharedMemorySize, GEMM_SMEM);
    cudaFuncSetAttribute(flash_mma,  cudaFuncAttributeMaxDynamicSharedMemorySize, FLASH_SMEM);

    dim3 gblk(256);
    dim3 ggrid(HID / 128, ROWS / 128);          // (8, 128)

    split_act<<<ROWS * HID / 4 / 256, 256>>>(x);
    wsplit_all<<<dim3(32, 32, 4), dim3(32, 8)>>>(wq, wk, wv, wo);

    tc_gemm<0><<<ggrid, gblk, GEMM_SMEM>>>(bq, nullptr);
    tc_gemm<1><<<ggrid, gblk, GEMM_SMEM>>>(bk, nullptr);
    tc_gemm<2><<<ggrid, gblk, GEMM_SMEM>>>(bv, nullptr);

    flash_mma<<<dim3(SEQ / 128, NHEADS, BATCH), 256, FLASH_SMEM>>>();

    tc_gemm<3><<<ggrid, gblk, GEMM_SMEM>>>(bo, out);
}